// round 3
// baseline (speedup 1.0000x reference)
#include <cuda_runtime.h>
#include <math.h>

// ---------------------------------------------------------------------------
// Problem constants
//   x:      (8, 32, 32, 512)  -> rows = 8192, c = 512
//   w_qkv:  (512, 1536)   q/k/v interleaved per head: j = h*192 + part*64 + d
//   attention: b=8, heads=8, n=1024, dh=64, scale = 8^-0.5
//   w_out:  (512, 512), b_out: (512,)
// ---------------------------------------------------------------------------

// Scratch (static device globals; allocation inside kernel_launch is forbidden)
__device__ float g_Q[8 * 8 * 64 * 1024];   // [b][h][d][n]  (transposed for attn)
__device__ float g_K[8 * 8 * 64 * 1024];   // [b][h][d][n]
__device__ float g_V[8 * 8 * 1024 * 64];   // [b][h][n][d]
__device__ float g_O[8192 * 512];          // [b*n][h*64+d]

// FMA-only exp (MUFU on sm_103a is ~0.5 op/cyc/SM; 67M exps would dominate).
// exp(x) = 2^(x*log2e); range reduce, deg-5 Taylor in t = f*ln2, |t| <= 0.347.
__device__ __forceinline__ float fast_exp(float x) {
    float y = x * 1.4426950408889634f;
    y = fmaxf(y, -126.0f);
    y = fminf(y, 126.0f);
    float nf = rintf(y);
    float f = y - nf;                 // [-0.5, 0.5]
    float t = f * 0.6931471805599453f;
    float p = 8.3333337e-3f;          // 1/120
    p = fmaf(p, t, 4.1666668e-2f);    // 1/24
    p = fmaf(p, t, 0.16666667f);
    p = fmaf(p, t, 0.5f);
    p = fmaf(p, t, 1.0f);
    p = fmaf(p, t, 1.0f);
    int ni = (int)nf;
    return p * __int_as_float((ni + 127) << 23);
}

// ---------------------------------------------------------------------------
// Kernel 1: QKV projection.  C(8192,1536) = x(8192,512) @ w_qkv(512,1536)
// 128x128 block tile, BK=8, 256 threads, 8x8 per-thread microtile.
// Epilogue scatters into g_Q/g_K/g_V layouts.
// ---------------------------------------------------------------------------
__global__ __launch_bounds__(256) void qkv_gemm(const float* __restrict__ A,
                                                const float* __restrict__ B) {
    __shared__ float As[8][132];   // transposed A tile, padded (conflict-free)
    __shared__ float Bs[8][128];

    const int tid = threadIdx.x;
    const int ty = tid >> 4, tx = tid & 15;
    const int row0 = blockIdx.y * 128;
    const int col0 = blockIdx.x * 128;

    float acc[8][8];
#pragma unroll
    for (int i = 0; i < 8; i++)
#pragma unroll
        for (int j = 0; j < 8; j++) acc[i][j] = 0.0f;

    const int ar = tid >> 1, ac = (tid & 1) << 2;      // A: 128 rows x 8 cols
    const int br = tid >> 5, bc = (tid & 31) << 2;     // B: 8 rows x 128 cols
    const float* Aptr = A + (size_t)(row0 + ar) * 512 + ac;
    const float* Bptr = B + (size_t)br * 1536 + col0 + bc;

    for (int k0 = 0; k0 < 512; k0 += 8) {
        float4 av = *(const float4*)(Aptr + k0);
        float4 bv = *(const float4*)(Bptr + (size_t)k0 * 1536);
        __syncthreads();
        As[ac + 0][ar] = av.x; As[ac + 1][ar] = av.y;
        As[ac + 2][ar] = av.z; As[ac + 3][ar] = av.w;
        *(float4*)&Bs[br][bc] = bv;
        __syncthreads();
#pragma unroll
        for (int kk = 0; kk < 8; kk++) {
            float4 a0 = *(float4*)&As[kk][ty * 8];
            float4 a1 = *(float4*)&As[kk][ty * 8 + 4];
            float4 b0 = *(float4*)&Bs[kk][tx * 8];
            float4 b1 = *(float4*)&Bs[kk][tx * 8 + 4];
            float a[8] = {a0.x, a0.y, a0.z, a0.w, a1.x, a1.y, a1.z, a1.w};
            float b[8] = {b0.x, b0.y, b0.z, b0.w, b1.x, b1.y, b1.z, b1.w};
#pragma unroll
            for (int i = 0; i < 8; i++)
#pragma unroll
                for (int j = 0; j < 8; j++)
                    acc[i][j] = fmaf(a[i], b[j], acc[i][j]);
        }
    }

    // Scatter epilogue. j group of 8 never crosses a part/head boundary (8|64).
    const int j0 = col0 + tx * 8;
    const int h = j0 / 192;
    const int part = (j0 % 192) >> 6;
    const int d0 = j0 & 63;
    const int rowg0 = row0 + ty * 8;          // 8 rows stay within one b (8|1024)
    const int b_idx = rowg0 >> 10;
    const int n0 = rowg0 & 1023;
    const int bh = b_idx * 8 + h;

    if (part < 2) {
        float* dst = (part == 0 ? g_Q : g_K) + (size_t)bh * 64 * 1024;
#pragma unroll
        for (int c = 0; c < 8; c++) {
            int d = d0 + c;
            *(float4*)&dst[(size_t)d * 1024 + n0] =
                make_float4(acc[0][c], acc[1][c], acc[2][c], acc[3][c]);
            *(float4*)&dst[(size_t)d * 1024 + n0 + 4] =
                make_float4(acc[4][c], acc[5][c], acc[6][c], acc[7][c]);
        }
    } else {
        float* dst = g_V + ((size_t)bh * 1024) * 64 + d0;
#pragma unroll
        for (int r = 0; r < 8; r++) {
            *(float4*)&dst[(size_t)(n0 + r) * 64] =
                make_float4(acc[r][0], acc[r][1], acc[r][2], acc[r][3]);
            *(float4*)&dst[(size_t)(n0 + r) * 64 + 4] =
                make_float4(acc[r][4], acc[r][5], acc[r][6], acc[r][7]);
        }
    }
}

// ---------------------------------------------------------------------------
// Kernel 2: fused flash attention per (b,h).
// Block: 256 threads (16x16), BM=128 q-rows, j streamed in tiles of 128.
// smem: Qs[64][128] Ks[64][128] Vs[128][68] Ps[128][132] = ~164 KB dynamic.
// ---------------------------------------------------------------------------
__global__ __launch_bounds__(256) void attn_kernel() {
    extern __shared__ float sm[];
    float* Qs = sm;                    // [d][i]  64 x 128
    float* Ks = Qs + 64 * 128;         // [d][j]  64 x 128
    float* Vs = Ks + 64 * 128;         // [j][d]  128 x 68 (padded)
    float* Ps = Vs + 128 * 68;         // [i][j]  128 x 132 (padded)

    const int tid = threadIdx.x;
    const int ty = tid >> 4, tx = tid & 15;
    const int bh = blockIdx.y;
    const int i0blk = blockIdx.x * 128;
    const float* Qt = g_Q + (size_t)bh * 64 * 1024;
    const float* Kt = g_K + (size_t)bh * 64 * 1024;
    const float* Vt = g_V + (size_t)bh * 1024 * 64;
    const int iloc = ty * 8, jloc = tx * 8;
    const float scale = 0.35355339059327373f;   // 8^-0.5 (batch size!)

    // Load Q tile (128 rows x 64 d), already transposed in gmem.
#pragma unroll
    for (int c = 0; c < 8; c++) {
        int f4 = c * 256 + tid;
        int d = f4 >> 5, i4 = (f4 & 31) << 2;
        *(float4*)&Qs[d * 128 + i4] = *(const float4*)&Qt[(size_t)d * 1024 + i0blk + i4];
    }

    float Oa[8][4];
    float mrow[8], lrow[8];
#pragma unroll
    for (int r = 0; r < 8; r++) {
        mrow[r] = -1e30f; lrow[r] = 0.0f;
#pragma unroll
        for (int c = 0; c < 4; c++) Oa[r][c] = 0.0f;
    }

    for (int jt = 0; jt < 8; jt++) {
        const int j0 = jt * 128;
        // Load K tile
#pragma unroll
        for (int c = 0; c < 8; c++) {
            int f4 = c * 256 + tid;
            int d = f4 >> 5, j4 = (f4 & 31) << 2;
            *(float4*)&Ks[d * 128 + j4] = *(const float4*)&Kt[(size_t)d * 1024 + j0 + j4];
        }
        __syncthreads();

        // S tile: 8x8 per thread over d=64
        float S[8][8];
#pragma unroll
        for (int i = 0; i < 8; i++)
#pragma unroll
            for (int j = 0; j < 8; j++) S[i][j] = 0.0f;

#pragma unroll 8
        for (int d = 0; d < 64; d++) {
            float4 qa = *(float4*)&Qs[d * 128 + iloc];
            float4 qb = *(float4*)&Qs[d * 128 + iloc + 4];
            float4 ka = *(float4*)&Ks[d * 128 + jloc];
            float4 kb = *(float4*)&Ks[d * 128 + jloc + 4];
            float a[8] = {qa.x, qa.y, qa.z, qa.w, qb.x, qb.y, qb.z, qb.w};
            float b[8] = {ka.x, ka.y, ka.z, ka.w, kb.x, kb.y, kb.z, kb.w};
#pragma unroll
            for (int i = 0; i < 8; i++)
#pragma unroll
                for (int j = 0; j < 8; j++)
                    S[i][j] = fmaf(a[i], b[j], S[i][j]);
        }

        // Online softmax update. Row r is owned by the 16 lanes sharing ty
        // (contiguous 16-lane segment of the warp -> shfl width 16).
#pragma unroll
        for (int r = 0; r < 8; r++) {
            float rmax = -1e30f;
#pragma unroll
            for (int c = 0; c < 8; c++) { S[r][c] *= scale; rmax = fmaxf(rmax, S[r][c]); }
#pragma unroll
            for (int off = 8; off > 0; off >>= 1)
                rmax = fmaxf(rmax, __shfl_xor_sync(0xffffffffu, rmax, off, 16));
            float mnew = fmaxf(mrow[r], rmax);
            float corr = fast_exp(mrow[r] - mnew);
            float rsum = 0.0f;
#pragma unroll
            for (int c = 0; c < 8; c++) {
                float pv = fast_exp(S[r][c] - mnew);
                S[r][c] = pv;
                rsum += pv;
            }
#pragma unroll
            for (int off = 8; off > 0; off >>= 1)
                rsum += __shfl_xor_sync(0xffffffffu, rsum, off, 16);
            lrow[r] = lrow[r] * corr + rsum;
            mrow[r] = mnew;
#pragma unroll
            for (int c = 0; c < 4; c++) Oa[r][c] *= corr;
        }

        // Write P (natural [i][j], vectorized along j -> conflict-free STS.128)
#pragma unroll
        for (int r = 0; r < 8; r++) {
            *(float4*)&Ps[(iloc + r) * 132 + jloc] =
                make_float4(S[r][0], S[r][1], S[r][2], S[r][3]);
            *(float4*)&Ps[(iloc + r) * 132 + jloc + 4] =
                make_float4(S[r][4], S[r][5], S[r][6], S[r][7]);
        }
        // Load V tile (independent buffer; covered by the same barrier)
#pragma unroll
        for (int c = 0; c < 8; c++) {
            int f4 = c * 256 + tid;
            int j = f4 >> 4, dq = (f4 & 15) << 2;
            *(float4*)&Vs[j * 68 + dq] = *(const float4*)&Vt[(size_t)(j0 + j) * 64 + dq];
        }
        __syncthreads();

        // O += P @ V   (thread: 8 rows x 4 d-cols)
#pragma unroll 4
        for (int j = 0; j < 128; j++) {
            float4 bv = *(float4*)&Vs[j * 68 + tx * 4];
            float av[8];
#pragma unroll
            for (int r = 0; r < 8; r++) av[r] = Ps[(iloc + r) * 132 + j];
#pragma unroll
            for (int r = 0; r < 8; r++) {
                Oa[r][0] = fmaf(av[r], bv.x, Oa[r][0]);
                Oa[r][1] = fmaf(av[r], bv.y, Oa[r][1]);
                Oa[r][2] = fmaf(av[r], bv.z, Oa[r][2]);
                Oa[r][3] = fmaf(av[r], bv.w, Oa[r][3]);
            }
        }
        __syncthreads();
    }

    // Epilogue: normalize, write to g_O[(b*1024+i)][h*64+d]
    const int b_idx = bh >> 3, h = bh & 7;
#pragma unroll
    for (int r = 0; r < 8; r++) {
        float inv = 1.0f / lrow[r];
        size_t rowg = (size_t)b_idx * 1024 + i0blk + iloc + r;
        *(float4*)&g_O[rowg * 512 + h * 64 + tx * 4] =
            make_float4(Oa[r][0] * inv, Oa[r][1] * inv, Oa[r][2] * inv, Oa[r][3] * inv);
    }
}

// ---------------------------------------------------------------------------
// Kernel 3: output projection.  out(8192,512) = g_O @ w_out + b_out
// ---------------------------------------------------------------------------
__global__ __launch_bounds__(256) void out_gemm(const float* __restrict__ B,
                                                const float* __restrict__ bias,
                                                float* __restrict__ C) {
    __shared__ float As[8][132];
    __shared__ float Bs[8][128];

    const int tid = threadIdx.x;
    const int ty = tid >> 4, tx = tid & 15;
    const int row0 = blockIdx.y * 128;
    const int col0 = blockIdx.x * 128;

    float acc[8][8];
#pragma unroll
    for (int i = 0; i < 8; i++)
#pragma unroll
        for (int j = 0; j < 8; j++) acc[i][j] = 0.0f;

    const int ar = tid >> 1, ac = (tid & 1) << 2;
    const int br = tid >> 5, bc = (tid & 31) << 2;
    const float* Aptr = g_O + (size_t)(row0 + ar) * 512 + ac;
    const float* Bptr = B + (size_t)br * 512 + col0 + bc;

    for (int k0 = 0; k0 < 512; k0 += 8) {
        float4 av = *(const float4*)(Aptr + k0);
        float4 bv = *(const float4*)(Bptr + (size_t)k0 * 512);
        __syncthreads();
        As[ac + 0][ar] = av.x; As[ac + 1][ar] = av.y;
        As[ac + 2][ar] = av.z; As[ac + 3][ar] = av.w;
        *(float4*)&Bs[br][bc] = bv;
        __syncthreads();
#pragma unroll
        for (int kk = 0; kk < 8; kk++) {
            float4 a0 = *(float4*)&As[kk][ty * 8];
            float4 a1 = *(float4*)&As[kk][ty * 8 + 4];
            float4 b0 = *(float4*)&Bs[kk][tx * 8];
            float4 b1 = *(float4*)&Bs[kk][tx * 8 + 4];
            float a[8] = {a0.x, a0.y, a0.z, a0.w, a1.x, a1.y, a1.z, a1.w};
            float b[8] = {b0.x, b0.y, b0.z, b0.w, b1.x, b1.y, b1.z, b1.w};
#pragma unroll
            for (int i = 0; i < 8; i++)
#pragma unroll
                for (int j = 0; j < 8; j++)
                    acc[i][j] = fmaf(a[i], b[j], acc[i][j]);
        }
    }

    float4 bi0 = *(const float4*)&bias[col0 + tx * 8];
    float4 bi1 = *(const float4*)&bias[col0 + tx * 8 + 4];
#pragma unroll
    for (int r = 0; r < 8; r++) {
        size_t rowg = (size_t)(row0 + ty * 8 + r);
        *(float4*)&C[rowg * 512 + col0 + tx * 8] =
            make_float4(acc[r][0] + bi0.x, acc[r][1] + bi0.y,
                        acc[r][2] + bi0.z, acc[r][3] + bi0.w);
        *(float4*)&C[rowg * 512 + col0 + tx * 8 + 4] =
            make_float4(acc[r][4] + bi1.x, acc[r][5] + bi1.y,
                        acc[r][6] + bi1.z, acc[r][7] + bi1.w);
    }
}

// ---------------------------------------------------------------------------
extern "C" void kernel_launch(void* const* d_in, const int* in_sizes, int n_in,
                              void* d_out, int out_size) {
    const float* x     = (const float*)d_in[0];
    const float* w_qkv = (const float*)d_in[1];
    const float* w_out = (const float*)d_in[2];
    const float* b_out = (const float*)d_in[3];
    float* out = (float*)d_out;

    const size_t attn_smem =
        (size_t)(64 * 128 + 64 * 128 + 128 * 68 + 128 * 132) * sizeof(float);
    cudaFuncSetAttribute(attn_kernel, cudaFuncAttributeMaxDynamicSharedMemorySize,
                         (int)attn_smem);

    qkv_gemm<<<dim3(12, 64), 256>>>(x, w_qkv);
    attn_kernel<<<dim3(8, 64), 256, attn_smem>>>();
    out_gemm<<<dim3(4, 64), 256>>>(w_out, b_out, out);
}

// round 6
// speedup vs baseline: 1.2460x; 1.2460x over previous
#include <cuda_runtime.h>
#include <cuda_bf16.h>
#include <math.h>
#include <stdint.h>

// ---------------------------------------------------------------------------
// Problem: x(8192,512) @ w_qkv(512,1536) -> 64-head attention (n=1024, dh=64,
// scale = 8^-0.5) -> @ w_out(512,512) + b_out.  fp32 in/out, rel_err < 1e-3.
// This round: projections on tensor cores (bf16x3, split done IN-KERNEL from
// fp32 gmem; no prepass kernels, no bf16 staging globals). Attention is the
// verbatim round-1 fp32 SIMT kernel (proven).
// ---------------------------------------------------------------------------

__device__ alignas(16) float g_Q[8 * 8 * 64 * 1024];   // [bh][d][n]
__device__ alignas(16) float g_K[8 * 8 * 64 * 1024];   // [bh][d][n]
__device__ alignas(16) float g_V[8 * 8 * 1024 * 64];   // [bh][n][d]
__device__ alignas(16) float g_O[8192 * 512];          // [b*n][h*64+d]

// ---------------------------------------------------------------------------
// FMA-only exp (MUFU rt=8/SMSP would bottleneck 67M softmax exps)
__device__ __forceinline__ float fast_exp(float x) {
    float y = x * 1.4426950408889634f;
    y = fmaxf(y, -126.0f);
    y = fminf(y, 126.0f);
    float nf = rintf(y);
    float t = (y - nf) * 0.6931471805599453f;
    float p = 8.3333337e-3f;
    p = fmaf(p, t, 4.1666668e-2f);
    p = fmaf(p, t, 0.16666667f);
    p = fmaf(p, t, 0.5f);
    p = fmaf(p, t, 1.0f);
    p = fmaf(p, t, 1.0f);
    return p * __int_as_float(((int)nf + 127) << 23);
}

// ---------------------------------------------------------------------------
// mma / ldmatrix primitives
__device__ __forceinline__ void ldsm4(uint32_t r[4], const void* p) {
    uint32_t a = (uint32_t)__cvta_generic_to_shared(p);
    asm volatile("ldmatrix.sync.aligned.m8n8.x4.shared.b16 {%0,%1,%2,%3}, [%4];"
                 : "=r"(r[0]), "=r"(r[1]), "=r"(r[2]), "=r"(r[3]) : "r"(a));
}
__device__ __forceinline__ void mma_bf16(float c[4], const uint32_t a[4],
                                         uint32_t b0, uint32_t b1) {
    asm volatile(
        "mma.sync.aligned.m16n8k16.row.col.f32.bf16.bf16.f32 "
        "{%0,%1,%2,%3}, {%4,%5,%6,%7}, {%8,%9}, {%0,%1,%2,%3};"
        : "+f"(c[0]), "+f"(c[1]), "+f"(c[2]), "+f"(c[3])
        : "r"(a[0]), "r"(a[1]), "r"(a[2]), "r"(a[3]), "r"(b0), "r"(b1));
}
__device__ __forceinline__ uint32_t split2(float v0, float v1, uint32_t& lo) {
    __nv_bfloat162 h, l;
    h.x = __float2bfloat16(v0);
    h.y = __float2bfloat16(v1);
    l.x = __float2bfloat16(v0 - __bfloat162float(h.x));
    l.y = __float2bfloat16(v1 - __bfloat162float(h.y));
    lo = *reinterpret_cast<uint32_t*>(&l);
    return *reinterpret_cast<uint32_t*>(&h);
}

// ---------------------------------------------------------------------------
// 128x128 block (K=512, chunk 64) bf16x3 mma mainloop, fp32 sources.
// A: fp32 [m][512] row-major. B: fp32 [512][ncols] row-major (k-major rows);
// transposed in-kernel into K-major smem. 256 threads = 8 warps (2x4),
// warp tile 64x32. Smem: 4 x [128][72] bf16 = 73728 B.
__device__ __forceinline__ void gemm_mainloop32(
    const float* __restrict__ Ag, const float* __restrict__ Bg, int ncols,
    int row0, int col0, char* sm, float c[4][4][4]) {
    __nv_bfloat16* sAh = (__nv_bfloat16*)sm;        // [128][72]  (m, k)
    __nv_bfloat16* sAl = sAh + 128 * 72;
    __nv_bfloat16* sBh = sAl + 128 * 72;            // [128][72]  (n, k)
    __nv_bfloat16* sBl = sBh + 128 * 72;
    const int tid = threadIdx.x, lane = tid & 31, warp = tid >> 5;
    const int wy = warp >> 2, wx = warp & 3;
    const int lr = lane & 15, lc = (lane >> 4) * 8;

    for (int kc = 0; kc < 512; kc += 64) {
        __syncthreads();
        // A tile: 128 rows x 64 k, 2 consecutive k per thread-item
#pragma unroll
        for (int i = 0; i < 16; i++) {
            int item = i * 256 + tid;
            int r = item >> 5, cc = (item & 31) * 2;
            float2 v = *(const float2*)&Ag[(size_t)(row0 + r) * 512 + kc + cc];
            uint32_t lo, hi = split2(v.x, v.y, lo);
            *(uint32_t*)&sAh[r * 72 + cc] = hi;
            *(uint32_t*)&sAl[r * 72 + cc] = lo;
        }
        // B tile: transpose W[k][n] -> smem[n][k], 2 consecutive k per item
#pragma unroll
        for (int i = 0; i < 16; i++) {
            int item = i * 256 + tid;
            int cn = item & 127, r = (item >> 7) * 2;
            float v0 = Bg[(size_t)(kc + r) * ncols + col0 + cn];
            float v1 = Bg[(size_t)(kc + r + 1) * ncols + col0 + cn];
            uint32_t lo, hi = split2(v0, v1, lo);
            *(uint32_t*)&sBh[cn * 72 + r] = hi;
            *(uint32_t*)&sBl[cn * 72 + r] = lo;
        }
        __syncthreads();
#pragma unroll
        for (int kt = 0; kt < 4; kt++) {
            uint32_t ah[4][4], al[4][4];
#pragma unroll
            for (int mt = 0; mt < 4; mt++) {
                int ro = (wy * 64 + mt * 16 + lr) * 72 + kt * 16 + lc;
                ldsm4(ah[mt], &sAh[ro]);
                ldsm4(al[mt], &sAl[ro]);
            }
#pragma unroll
            for (int nt16 = 0; nt16 < 2; nt16++) {
                uint32_t bh[4], bl[4];
                int ro = (wx * 32 + nt16 * 16 + lr) * 72 + kt * 16 + lc;
                ldsm4(bh, &sBh[ro]);
                ldsm4(bl, &sBl[ro]);
#pragma unroll
                for (int mt = 0; mt < 4; mt++) {
                    float* c0 = c[mt][nt16 * 2];
                    float* c1 = c[mt][nt16 * 2 + 1];
                    mma_bf16(c0, ah[mt], bh[0], bh[2]);
                    mma_bf16(c0, ah[mt], bl[0], bl[2]);
                    mma_bf16(c0, al[mt], bh[0], bh[2]);
                    mma_bf16(c1, ah[mt], bh[1], bh[3]);
                    mma_bf16(c1, ah[mt], bl[1], bl[3]);
                    mma_bf16(c1, al[mt], bh[1], bh[3]);
                }
            }
        }
    }
}

// ---------------------------------------------------------------------------
// Kernel 1: QKV projection (mma) -> scatter fp32 Q/K ([bh][d][n]), V ([bh][n][d])
__global__ __launch_bounds__(256) void qkv_gemm_mma(const float* __restrict__ x,
                                                    const float* __restrict__ w) {
    extern __shared__ char sm[];
    float c[4][4][4];
#pragma unroll
    for (int a = 0; a < 4; a++)
#pragma unroll
        for (int b = 0; b < 4; b++)
#pragma unroll
            for (int d = 0; d < 4; d++) c[a][b][d] = 0.0f;

    const int row0 = blockIdx.y * 128, col0 = blockIdx.x * 128;
    gemm_mainloop32(x, w, 1536, row0, col0, sm, c);

    // Stage frags to fp32 smem tile, then round-1's verified scatter.
    float* Cs = (float*)sm;
    __syncthreads();
    const int lane = threadIdx.x & 31, warp = threadIdx.x >> 5;
    const int wy = warp >> 2, wx = warp & 3, g = lane >> 2, tig = lane & 3;
#pragma unroll
    for (int mt = 0; mt < 4; mt++)
#pragma unroll
        for (int nt = 0; nt < 4; nt++) {
            int r = wy * 64 + mt * 16 + g, cc = wx * 32 + nt * 8 + tig * 2;
            Cs[r * 132 + cc] = c[mt][nt][0];
            Cs[r * 132 + cc + 1] = c[mt][nt][1];
            Cs[(r + 8) * 132 + cc] = c[mt][nt][2];
            Cs[(r + 8) * 132 + cc + 1] = c[mt][nt][3];
        }
    __syncthreads();

    const int tid = threadIdx.x;
    const int ty = tid >> 4, tx = tid & 15;
    const int jloc = tx * 8, j0 = col0 + jloc;
    const int h = j0 / 192, part = (j0 % 192) >> 6, d0 = j0 & 63;
    const int rowg0 = row0 + ty * 8;
    const int b_idx = rowg0 >> 10, n0 = rowg0 & 1023, bh = b_idx * 8 + h;

    float v[8][8];
#pragma unroll
    for (int r = 0; r < 8; r++)
#pragma unroll
        for (int k = 0; k < 8; k++) v[r][k] = Cs[(ty * 8 + r) * 132 + jloc + k];

    if (part < 2) {
        float* dst = (part == 0 ? g_Q : g_K) + (size_t)bh * 64 * 1024;
#pragma unroll
        for (int k = 0; k < 8; k++) {
            int d = d0 + k;
            *(float4*)&dst[(size_t)d * 1024 + n0] =
                make_float4(v[0][k], v[1][k], v[2][k], v[3][k]);
            *(float4*)&dst[(size_t)d * 1024 + n0 + 4] =
                make_float4(v[4][k], v[5][k], v[6][k], v[7][k]);
        }
    } else {
        float* dst = g_V + ((size_t)bh * 1024) * 64 + d0;
#pragma unroll
        for (int r = 0; r < 8; r++) {
            *(float4*)&dst[(size_t)(n0 + r) * 64] =
                make_float4(v[r][0], v[r][1], v[r][2], v[r][3]);
            *(float4*)&dst[(size_t)(n0 + r) * 64 + 4] =
                make_float4(v[r][4], v[r][5], v[r][6], v[r][7]);
        }
    }
}

// ---------------------------------------------------------------------------
// Kernel 2: fused flash attention per (b,h) — verbatim round-1 (proven).
__global__ __launch_bounds__(256) void attn_kernel() {
    extern __shared__ float smf[];
    float* Qs = smf;                   // [d][i]  64 x 128
    float* Ks = Qs + 64 * 128;         // [d][j]  64 x 128
    float* Vs = Ks + 64 * 128;         // [j][d]  128 x 68 (padded)
    float* Ps = Vs + 128 * 68;         // [i][j]  128 x 132 (padded)

    const int tid = threadIdx.x;
    const int ty = tid >> 4, tx = tid & 15;
    const int bh = blockIdx.y;
    const int i0blk = blockIdx.x * 128;
    const float* Qt = g_Q + (size_t)bh * 64 * 1024;
    const float* Kt = g_K + (size_t)bh * 64 * 1024;
    const float* Vt = g_V + (size_t)bh * 1024 * 64;
    const int iloc = ty * 8, jloc = tx * 8;
    const float scale = 0.35355339059327373f;   // 8^-0.5 (batch-size scale!)

#pragma unroll
    for (int c = 0; c < 8; c++) {
        int f4 = c * 256 + tid;
        int d = f4 >> 5, i4 = (f4 & 31) << 2;
        *(float4*)&Qs[d * 128 + i4] = *(const float4*)&Qt[(size_t)d * 1024 + i0blk + i4];
    }

    float Oa[8][4];
    float mrow[8], lrow[8];
#pragma unroll
    for (int r = 0; r < 8; r++) {
        mrow[r] = -1e30f; lrow[r] = 0.0f;
#pragma unroll
        for (int c = 0; c < 4; c++) Oa[r][c] = 0.0f;
    }

    for (int jt = 0; jt < 8; jt++) {
        const int j0 = jt * 128;
#pragma unroll
        for (int c = 0; c < 8; c++) {
            int f4 = c * 256 + tid;
            int d = f4 >> 5, j4 = (f4 & 31) << 2;
            *(float4*)&Ks[d * 128 + j4] = *(const float4*)&Kt[(size_t)d * 1024 + j0 + j4];
        }
        __syncthreads();

        float S[8][8];
#pragma unroll
        for (int i = 0; i < 8; i++)
#pragma unroll
            for (int j = 0; j < 8; j++) S[i][j] = 0.0f;

#pragma unroll 8
        for (int d = 0; d < 64; d++) {
            float4 qa = *(float4*)&Qs[d * 128 + iloc];
            float4 qb = *(float4*)&Qs[d * 128 + iloc + 4];
            float4 ka = *(float4*)&Ks[d * 128 + jloc];
            float4 kb = *(float4*)&Ks[d * 128 + jloc + 4];
            float a[8] = {qa.x, qa.y, qa.z, qa.w, qb.x, qb.y, qb.z, qb.w};
            float b[8] = {ka.x, ka.y, ka.z, ka.w, kb.x, kb.y, kb.z, kb.w};
#pragma unroll
            for (int i = 0; i < 8; i++)
#pragma unroll
                for (int j = 0; j < 8; j++)
                    S[i][j] = fmaf(a[i], b[j], S[i][j]);
        }

#pragma unroll
        for (int r = 0; r < 8; r++) {
            float rmax = -1e30f;
#pragma unroll
            for (int c = 0; c < 8; c++) { S[r][c] *= scale; rmax = fmaxf(rmax, S[r][c]); }
#pragma unroll
            for (int off = 8; off > 0; off >>= 1)
                rmax = fmaxf(rmax, __shfl_xor_sync(0xffffffffu, rmax, off, 16));
            float mnew = fmaxf(mrow[r], rmax);
            float corr = fast_exp(mrow[r] - mnew);
            float rsum = 0.0f;
#pragma unroll
            for (int c = 0; c < 8; c++) {
                float pv = fast_exp(S[r][c] - mnew);
                S[r][c] = pv;
                rsum += pv;
            }
#pragma unroll
            for (int off = 8; off > 0; off >>= 1)
                rsum += __shfl_xor_sync(0xffffffffu, rsum, off, 16);
            lrow[r] = lrow[r] * corr + rsum;
            mrow[r] = mnew;
#pragma unroll
            for (int c = 0; c < 4; c++) Oa[r][c] *= corr;
        }

#pragma unroll
        for (int r = 0; r < 8; r++) {
            *(float4*)&Ps[(iloc + r) * 132 + jloc] =
                make_float4(S[r][0], S[r][1], S[r][2], S[r][3]);
            *(float4*)&Ps[(iloc + r) * 132 + jloc + 4] =
                make_float4(S[r][4], S[r][5], S[r][6], S[r][7]);
        }
#pragma unroll
        for (int c = 0; c < 8; c++) {
            int f4 = c * 256 + tid;
            int j = f4 >> 4, dq = (f4 & 15) << 2;
            *(float4*)&Vs[j * 68 + dq] = *(const float4*)&Vt[(size_t)(j0 + j) * 64 + dq];
        }
        __syncthreads();

#pragma unroll 4
        for (int j = 0; j < 128; j++) {
            float4 bv = *(float4*)&Vs[j * 68 + tx * 4];
            float av[8];
#pragma unroll
            for (int r = 0; r < 8; r++) av[r] = Ps[(iloc + r) * 132 + j];
#pragma unroll
            for (int r = 0; r < 8; r++) {
                Oa[r][0] = fmaf(av[r], bv.x, Oa[r][0]);
                Oa[r][1] = fmaf(av[r], bv.y, Oa[r][1]);
                Oa[r][2] = fmaf(av[r], bv.z, Oa[r][2]);
                Oa[r][3] = fmaf(av[r], bv.w, Oa[r][3]);
            }
        }
        __syncthreads();
    }

    const int b_idx = bh >> 3, h = bh & 7;
#pragma unroll
    for (int r = 0; r < 8; r++) {
        float inv = 1.0f / lrow[r];
        size_t rowg = (size_t)b_idx * 1024 + i0blk + iloc + r;
        *(float4*)&g_O[rowg * 512 + h * 64 + tx * 4] =
            make_float4(Oa[r][0] * inv, Oa[r][1] * inv, Oa[r][2] * inv, Oa[r][3] * inv);
    }
}

// ---------------------------------------------------------------------------
// Kernel 3: output projection out = g_O @ w_out + b_out (bf16x3 mma, fp32 src)
__global__ __launch_bounds__(256) void out_gemm_mma(const float* __restrict__ w,
                                                    const float* __restrict__ bias,
                                                    float* __restrict__ out) {
    extern __shared__ char sm[];
    float c[4][4][4];
#pragma unroll
    for (int a = 0; a < 4; a++)
#pragma unroll
        for (int b = 0; b < 4; b++)
#pragma unroll
            for (int d = 0; d < 4; d++) c[a][b][d] = 0.0f;

    const int row0 = blockIdx.y * 128, col0 = blockIdx.x * 128;
    gemm_mainloop32(g_O, w, 512, row0, col0, sm, c);

    const int lane = threadIdx.x & 31, warp = threadIdx.x >> 5;
    const int wy = warp >> 2, wx = warp & 3, g = lane >> 2, tig = lane & 3;
#pragma unroll
    for (int mt = 0; mt < 4; mt++)
#pragma unroll
        for (int nt = 0; nt < 4; nt++) {
            int r = row0 + wy * 64 + mt * 16 + g;
            int cc = col0 + wx * 32 + nt * 8 + tig * 2;
            float b0 = bias[cc], b1 = bias[cc + 1];
            *(float2*)&out[(size_t)r * 512 + cc] =
                make_float2(c[mt][nt][0] + b0, c[mt][nt][1] + b1);
            *(float2*)&out[(size_t)(r + 8) * 512 + cc] =
                make_float2(c[mt][nt][2] + b0, c[mt][nt][3] + b1);
        }
}

// ---------------------------------------------------------------------------
extern "C" void kernel_launch(void* const* d_in, const int* in_sizes, int n_in,
                              void* d_out, int out_size) {
    const float* x     = (const float*)d_in[0];
    const float* w_qkv = (const float*)d_in[1];
    const float* w_out = (const float*)d_in[2];
    const float* b_out = (const float*)d_in[3];
    float* out = (float*)d_out;

    const int gemm_smem = 4 * 128 * 72 * 2;   // 73728 B (covers Cs 67584 B too)
    const int attn_smem = (64 * 128 + 64 * 128 + 128 * 68 + 128 * 132) * 4;  // 167936 B
    cudaFuncSetAttribute(qkv_gemm_mma, cudaFuncAttributeMaxDynamicSharedMemorySize, gemm_smem);
    cudaFuncSetAttribute(attn_kernel, cudaFuncAttributeMaxDynamicSharedMemorySize, attn_smem);
    cudaFuncSetAttribute(out_gemm_mma, cudaFuncAttributeMaxDynamicSharedMemorySize, gemm_smem);

    qkv_gemm_mma<<<dim3(12, 64), 256, gemm_smem>>>(x, w_qkv);
    attn_kernel<<<dim3(8, 64), 256, attn_smem>>>();
    out_gemm_mma<<<dim3(4, 64), 256, gemm_smem>>>(w_out, b_out, out);
}

// round 7
// speedup vs baseline: 2.3264x; 1.8670x over previous
#include <cuda_runtime.h>
#include <cuda_bf16.h>
#include <cuda_fp16.h>
#include <math.h>
#include <stdint.h>

// ---------------------------------------------------------------------------
// x(8192,512) @ w_qkv(512,1536) -> 64-head attention (n=1024, dh=64,
// scale=8^-0.5) -> @ w_out(512,512) + b_out. fp32 in/out, rel_err < 1e-3.
// All three matmul stages on tensor cores: bf16x3 projections + QK^T,
// fp16 P·V. NOTE: device globals are referenced ONLY from device code
// (passing them as launch args from host was the round-4/5 silent failure).
// ---------------------------------------------------------------------------

__device__ alignas(16) __nv_bfloat16 g_Qh[64 * 1024 * 64], g_Ql[64 * 1024 * 64]; // [bh][n][d]
__device__ alignas(16) __nv_bfloat16 g_Kh[64 * 1024 * 64], g_Kl[64 * 1024 * 64]; // [bh][n][d]
__device__ alignas(16) __half        g_Vf[64 * 1024 * 64];                       // [bh][n][d]
__device__ alignas(16) float g_O[8192 * 512];                                    // [b*n][h*64+d]

// ---------------------------------------------------------------------------
// FMA-only exp (MUFU rt=8/SMSP would bottleneck 67M softmax exps)
__device__ __forceinline__ float fast_exp(float x) {
    float y = x * 1.4426950408889634f;
    y = fmaxf(y, -126.0f);
    y = fminf(y, 126.0f);
    float nf = rintf(y);
    float t = (y - nf) * 0.6931471805599453f;
    float p = 8.3333337e-3f;
    p = fmaf(p, t, 4.1666668e-2f);
    p = fmaf(p, t, 0.16666667f);
    p = fmaf(p, t, 0.5f);
    p = fmaf(p, t, 1.0f);
    p = fmaf(p, t, 1.0f);
    return p * __int_as_float(((int)nf + 127) << 23);
}

// ---------------------------------------------------------------------------
// mma / ldmatrix primitives (proven in round 6)
__device__ __forceinline__ void ldsm4(uint32_t r[4], const void* p) {
    uint32_t a = (uint32_t)__cvta_generic_to_shared(p);
    asm volatile("ldmatrix.sync.aligned.m8n8.x4.shared.b16 {%0,%1,%2,%3}, [%4];"
                 : "=r"(r[0]), "=r"(r[1]), "=r"(r[2]), "=r"(r[3]) : "r"(a));
}
__device__ __forceinline__ void ldsm4t(uint32_t r[4], const void* p) {
    uint32_t a = (uint32_t)__cvta_generic_to_shared(p);
    asm volatile("ldmatrix.sync.aligned.m8n8.x4.trans.shared.b16 {%0,%1,%2,%3}, [%4];"
                 : "=r"(r[0]), "=r"(r[1]), "=r"(r[2]), "=r"(r[3]) : "r"(a));
}
__device__ __forceinline__ void mma_bf16(float c[4], const uint32_t a[4],
                                         uint32_t b0, uint32_t b1) {
    asm volatile(
        "mma.sync.aligned.m16n8k16.row.col.f32.bf16.bf16.f32 "
        "{%0,%1,%2,%3}, {%4,%5,%6,%7}, {%8,%9}, {%0,%1,%2,%3};"
        : "+f"(c[0]), "+f"(c[1]), "+f"(c[2]), "+f"(c[3])
        : "r"(a[0]), "r"(a[1]), "r"(a[2]), "r"(a[3]), "r"(b0), "r"(b1));
}
__device__ __forceinline__ void mma_f16(float c[4], const uint32_t a[4],
                                        uint32_t b0, uint32_t b1) {
    asm volatile(
        "mma.sync.aligned.m16n8k16.row.col.f32.f16.f16.f32 "
        "{%0,%1,%2,%3}, {%4,%5,%6,%7}, {%8,%9}, {%0,%1,%2,%3};"
        : "+f"(c[0]), "+f"(c[1]), "+f"(c[2]), "+f"(c[3])
        : "r"(a[0]), "r"(a[1]), "r"(a[2]), "r"(a[3]), "r"(b0), "r"(b1));
}
__device__ __forceinline__ uint32_t split2(float v0, float v1, uint32_t& lo) {
    __nv_bfloat162 h, l;
    h.x = __float2bfloat16(v0);
    h.y = __float2bfloat16(v1);
    l.x = __float2bfloat16(v0 - __bfloat162float(h.x));
    l.y = __float2bfloat16(v1 - __bfloat162float(h.y));
    lo = *reinterpret_cast<uint32_t*>(&l);
    return *reinterpret_cast<uint32_t*>(&h);
}
__device__ __forceinline__ uint32_t pack_half2(float lo, float hi) {
    __half2 h = __floats2half2_rn(lo, hi);
    return *reinterpret_cast<uint32_t*>(&h);
}

// ---------------------------------------------------------------------------
// 128x128 block (K=512, chunk 64) bf16x3 mma mainloop, fp32 sources (proven).
__device__ __forceinline__ void gemm_mainloop32(
    const float* __restrict__ Ag, const float* __restrict__ Bg, int ncols,
    int row0, int col0, char* sm, float c[4][4][4]) {
    __nv_bfloat16* sAh = (__nv_bfloat16*)sm;        // [128][72]  (m, k)
    __nv_bfloat16* sAl = sAh + 128 * 72;
    __nv_bfloat16* sBh = sAl + 128 * 72;            // [128][72]  (n, k)
    __nv_bfloat16* sBl = sBh + 128 * 72;
    const int tid = threadIdx.x, lane = tid & 31, warp = tid >> 5;
    const int wy = warp >> 2, wx = warp & 3;
    const int lr = lane & 15, lc = (lane >> 4) * 8;

    for (int kc = 0; kc < 512; kc += 64) {
        __syncthreads();
#pragma unroll
        for (int i = 0; i < 16; i++) {
            int item = i * 256 + tid;
            int r = item >> 5, cc = (item & 31) * 2;
            float2 v = *(const float2*)&Ag[(size_t)(row0 + r) * 512 + kc + cc];
            uint32_t lo, hi = split2(v.x, v.y, lo);
            *(uint32_t*)&sAh[r * 72 + cc] = hi;
            *(uint32_t*)&sAl[r * 72 + cc] = lo;
        }
#pragma unroll
        for (int i = 0; i < 16; i++) {
            int item = i * 256 + tid;
            int cn = item & 127, r = (item >> 7) * 2;
            float v0 = Bg[(size_t)(kc + r) * ncols + col0 + cn];
            float v1 = Bg[(size_t)(kc + r + 1) * ncols + col0 + cn];
            uint32_t lo, hi = split2(v0, v1, lo);
            *(uint32_t*)&sBh[cn * 72 + r] = hi;
            *(uint32_t*)&sBl[cn * 72 + r] = lo;
        }
        __syncthreads();
#pragma unroll
        for (int kt = 0; kt < 4; kt++) {
            uint32_t ah[4][4], al[4][4];
#pragma unroll
            for (int mt = 0; mt < 4; mt++) {
                int ro = (wy * 64 + mt * 16 + lr) * 72 + kt * 16 + lc;
                ldsm4(ah[mt], &sAh[ro]);
                ldsm4(al[mt], &sAl[ro]);
            }
#pragma unroll
            for (int nt16 = 0; nt16 < 2; nt16++) {
                uint32_t bh[4], bl[4];
                int ro = (wx * 32 + nt16 * 16 + lr) * 72 + kt * 16 + lc;
                ldsm4(bh, &sBh[ro]);
                ldsm4(bl, &sBl[ro]);
#pragma unroll
                for (int mt = 0; mt < 4; mt++) {
                    float* c0 = c[mt][nt16 * 2];
                    float* c1 = c[mt][nt16 * 2 + 1];
                    mma_bf16(c0, ah[mt], bh[0], bh[2]);
                    mma_bf16(c0, ah[mt], bl[0], bl[2]);
                    mma_bf16(c0, al[mt], bh[0], bh[2]);
                    mma_bf16(c1, ah[mt], bh[1], bh[3]);
                    mma_bf16(c1, ah[mt], bl[1], bl[3]);
                    mma_bf16(c1, al[mt], bh[1], bh[3]);
                }
            }
        }
    }
}

// ---------------------------------------------------------------------------
// Kernel 1: QKV projection -> Q/K bf16 hi/lo [bh][n][d] (Q pre-scaled), V fp16
__global__ __launch_bounds__(256) void qkv_gemm_mma(const float* __restrict__ x,
                                                    const float* __restrict__ w) {
    extern __shared__ char sm[];
    float c[4][4][4];
#pragma unroll
    for (int a = 0; a < 4; a++)
#pragma unroll
        for (int b = 0; b < 4; b++)
#pragma unroll
            for (int d = 0; d < 4; d++) c[a][b][d] = 0.0f;

    const int row0 = blockIdx.y * 128, col0 = blockIdx.x * 128;
    gemm_mainloop32(x, w, 1536, row0, col0, sm, c);

    float* Cs = (float*)sm;
    __syncthreads();
    const int lane = threadIdx.x & 31, warp = threadIdx.x >> 5;
    const int wy = warp >> 2, wx = warp & 3, g = lane >> 2, tig = lane & 3;
#pragma unroll
    for (int mt = 0; mt < 4; mt++)
#pragma unroll
        for (int nt = 0; nt < 4; nt++) {
            int r = wy * 64 + mt * 16 + g, cc = wx * 32 + nt * 8 + tig * 2;
            Cs[r * 132 + cc] = c[mt][nt][0];
            Cs[r * 132 + cc + 1] = c[mt][nt][1];
            Cs[(r + 8) * 132 + cc] = c[mt][nt][2];
            Cs[(r + 8) * 132 + cc + 1] = c[mt][nt][3];
        }
    __syncthreads();

    const int tid = threadIdx.x;
    const int ty = tid >> 4, tx = tid & 15;
    const int jloc = tx * 8, j0 = col0 + jloc;
    const int h = j0 / 192, part = (j0 % 192) >> 6, d0 = j0 & 63;
    const int rowg0 = row0 + ty * 8;
    const int b_idx = rowg0 >> 10, n0 = rowg0 & 1023, bh = b_idx * 8 + h;
    const float qs = 0.35355339059327373f;   // 8^-0.5 (batch-size scale!)

#pragma unroll
    for (int r = 0; r < 8; r++) {
        float v[8];
#pragma unroll
        for (int k = 0; k < 8; k++) v[k] = Cs[(ty * 8 + r) * 132 + jloc + k];
        size_t base = ((size_t)bh * 1024 + n0 + r) * 64 + d0;
        if (part == 0) {
            alignas(16) __nv_bfloat16 hh[8], ll[8];
#pragma unroll
            for (int k = 0; k < 8; k++) {
                float sv = v[k] * qs;
                hh[k] = __float2bfloat16(sv);
                ll[k] = __float2bfloat16(sv - __bfloat162float(hh[k]));
            }
            *(uint4*)&g_Qh[base] = *(const uint4*)hh;
            *(uint4*)&g_Ql[base] = *(const uint4*)ll;
        } else if (part == 1) {
            alignas(16) __nv_bfloat16 hh[8], ll[8];
#pragma unroll
            for (int k = 0; k < 8; k++) {
                hh[k] = __float2bfloat16(v[k]);
                ll[k] = __float2bfloat16(v[k] - __bfloat162float(hh[k]));
            }
            *(uint4*)&g_Kh[base] = *(const uint4*)hh;
            *(uint4*)&g_Kl[base] = *(const uint4*)ll;
        } else {
            alignas(16) __half hv[8];
#pragma unroll
            for (int k = 0; k < 8; k++) hv[k] = __float2half_rn(v[k]);
            *(uint4*)&g_Vf[base] = *(const uint4*)hv;
        }
    }
}

// ---------------------------------------------------------------------------
// Kernel 2: fused flash attention (tensor cores). 8 warps x 16 q-rows.
// S: bf16x3 mma; softmax on C-frags; P->A-frag repack; PV: fp16 mma.
__global__ __launch_bounds__(256) void attn_mma() {
    extern __shared__ char sm[];
    __nv_bfloat16* sQh = (__nv_bfloat16*)sm;       // [128][72]
    __nv_bfloat16* sQl = sQh + 128 * 72;
    __nv_bfloat16* sKh = sQl + 128 * 72;
    __nv_bfloat16* sKl = sKh + 128 * 72;
    __half* sV = (__half*)(sKl + 128 * 72);        // [128][72]

    const int tid = threadIdx.x, lane = tid & 31, warp = tid >> 5;
    const int g = lane >> 2, tig = lane & 3;
    const int lr = lane & 15, lc = (lane >> 4) * 8;
    const int vrow = ((lane >> 3) & 1) * 8 + (lane & 7);   // trans-ldsm addressing
    const int vcol = (lane >> 4) * 8;

    const int bh = blockIdx.y;
    const int i0 = blockIdx.x * 128;
    const size_t hb = (size_t)bh * 1024 * 64;

    // Load Q tile (resident all iterations)
#pragma unroll
    for (int i = 0; i < 4; i++) {
        int idx = i * 256 + tid;
        int r = idx >> 3, c16 = (idx & 7) * 8;
        *(uint4*)&sQh[r * 72 + c16] = *(const uint4*)&g_Qh[hb + (size_t)(i0 + r) * 64 + c16];
        *(uint4*)&sQl[r * 72 + c16] = *(const uint4*)&g_Ql[hb + (size_t)(i0 + r) * 64 + c16];
    }

    float o[8][4];
#pragma unroll
    for (int d = 0; d < 8; d++)
#pragma unroll
        for (int k = 0; k < 4; k++) o[d][k] = 0.0f;
    float m0 = -1e30f, m1 = -1e30f, l0 = 0.0f, l1 = 0.0f;

    for (int jt = 0; jt < 8; jt++) {
        const int j0 = jt * 128;
        if (jt) __syncthreads();           // previous iteration's smem reads done
#pragma unroll
        for (int i = 0; i < 4; i++) {
            int idx = i * 256 + tid;
            int r = idx >> 3, c16 = (idx & 7) * 8;
            *(uint4*)&sKh[r * 72 + c16] = *(const uint4*)&g_Kh[hb + (size_t)(j0 + r) * 64 + c16];
            *(uint4*)&sKl[r * 72 + c16] = *(const uint4*)&g_Kl[hb + (size_t)(j0 + r) * 64 + c16];
            *(uint4*)&sV[r * 72 + c16]  = *(const uint4*)&g_Vf[hb + (size_t)(j0 + r) * 64 + c16];
        }
        __syncthreads();

        // S = Q K^T over d=64 (4 k16 steps); warp rows warp*16..+15; 16 n8 tiles
        float s[16][4];
#pragma unroll
        for (int t = 0; t < 16; t++)
#pragma unroll
            for (int k = 0; k < 4; k++) s[t][k] = 0.0f;

#pragma unroll
        for (int kt = 0; kt < 4; kt++) {
            uint32_t qh[4], ql[4];
            int qo = (warp * 16 + lr) * 72 + kt * 16 + lc;
            ldsm4(qh, &sQh[qo]);
            ldsm4(ql, &sQl[qo]);
#pragma unroll
            for (int nt = 0; nt < 8; nt++) {
                uint32_t kh[4], kl[4];
                int ko = (nt * 16 + lr) * 72 + kt * 16 + lc;
                ldsm4(kh, &sKh[ko]);
                ldsm4(kl, &sKl[ko]);
                float* s0 = s[nt * 2];
                float* s1 = s[nt * 2 + 1];
                mma_bf16(s0, qh, kh[0], kh[2]);
                mma_bf16(s0, qh, kl[0], kl[2]);
                mma_bf16(s0, ql, kh[0], kh[2]);
                mma_bf16(s1, qh, kh[1], kh[3]);
                mma_bf16(s1, qh, kl[1], kl[3]);
                mma_bf16(s1, ql, kh[1], kh[3]);
            }
        }

        // Online softmax. Row pair: g (frag elems 0,1) and g+8 (elems 2,3);
        // each row spread over the 4 tig lanes (shfl xor 1,2).
        float rmax0 = -1e30f, rmax1 = -1e30f;
#pragma unroll
        for (int t = 0; t < 16; t++) {
            rmax0 = fmaxf(rmax0, fmaxf(s[t][0], s[t][1]));
            rmax1 = fmaxf(rmax1, fmaxf(s[t][2], s[t][3]));
        }
        rmax0 = fmaxf(rmax0, __shfl_xor_sync(0xffffffffu, rmax0, 1));
        rmax0 = fmaxf(rmax0, __shfl_xor_sync(0xffffffffu, rmax0, 2));
        rmax1 = fmaxf(rmax1, __shfl_xor_sync(0xffffffffu, rmax1, 1));
        rmax1 = fmaxf(rmax1, __shfl_xor_sync(0xffffffffu, rmax1, 2));
        float mn0 = fmaxf(m0, rmax0), mn1 = fmaxf(m1, rmax1);
        float cr0 = fast_exp(m0 - mn0), cr1 = fast_exp(m1 - mn1);
        float sum0 = 0.0f, sum1 = 0.0f;
#pragma unroll
        for (int t = 0; t < 16; t++) {
            s[t][0] = fast_exp(s[t][0] - mn0);
            s[t][1] = fast_exp(s[t][1] - mn0);
            s[t][2] = fast_exp(s[t][2] - mn1);
            s[t][3] = fast_exp(s[t][3] - mn1);
            sum0 += s[t][0] + s[t][1];
            sum1 += s[t][2] + s[t][3];
        }
        sum0 += __shfl_xor_sync(0xffffffffu, sum0, 1);
        sum0 += __shfl_xor_sync(0xffffffffu, sum0, 2);
        sum1 += __shfl_xor_sync(0xffffffffu, sum1, 1);
        sum1 += __shfl_xor_sync(0xffffffffu, sum1, 2);
        l0 = l0 * cr0 + sum0;
        l1 = l1 * cr1 + sum1;
        m0 = mn0;
        m1 = mn1;
#pragma unroll
        for (int d = 0; d < 8; d++) {
            o[d][0] *= cr0; o[d][1] *= cr0;
            o[d][2] *= cr1; o[d][3] *= cr1;
        }

        // O += P V   (P C-frag -> fp16 A-frag; V via ldmatrix.trans)
#pragma unroll
        for (int jt16 = 0; jt16 < 8; jt16++) {
            uint32_t a[4];
            a[0] = pack_half2(s[jt16 * 2][0], s[jt16 * 2][1]);
            a[1] = pack_half2(s[jt16 * 2][2], s[jt16 * 2][3]);
            a[2] = pack_half2(s[jt16 * 2 + 1][0], s[jt16 * 2 + 1][1]);
            a[3] = pack_half2(s[jt16 * 2 + 1][2], s[jt16 * 2 + 1][3]);
#pragma unroll
            for (int dt16 = 0; dt16 < 4; dt16++) {
                uint32_t v[4];
                ldsm4t(v, &sV[(jt16 * 16 + vrow) * 72 + dt16 * 16 + vcol]);
                mma_f16(o[dt16 * 2], a, v[0], v[1]);
                mma_f16(o[dt16 * 2 + 1], a, v[2], v[3]);
            }
        }
    }

    // Epilogue: normalize, write fp32 g_O [b*n][h*64+d]
    const float inv0 = 1.0f / l0, inv1 = 1.0f / l1;
    const int b_idx = bh >> 3, h = bh & 7;
    const size_t rowa = (size_t)b_idx * 1024 + i0 + warp * 16 + g;
    const size_t rowb = rowa + 8;
    const int colb = h * 64 + tig * 2;
#pragma unroll
    for (int dt = 0; dt < 8; dt++) {
        int col = colb + dt * 8;
        *(float2*)&g_O[rowa * 512 + col] = make_float2(o[dt][0] * inv0, o[dt][1] * inv0);
        *(float2*)&g_O[rowb * 512 + col] = make_float2(o[dt][2] * inv1, o[dt][3] * inv1);
    }
}

// ---------------------------------------------------------------------------
// Kernel 3: output projection out = g_O @ w_out + b_out (bf16x3 mma, proven)
__global__ __launch_bounds__(256) void out_gemm_mma(const float* __restrict__ w,
                                                    const float* __restrict__ bias,
                                                    float* __restrict__ out) {
    extern __shared__ char sm[];
    float c[4][4][4];
#pragma unroll
    for (int a = 0; a < 4; a++)
#pragma unroll
        for (int b = 0; b < 4; b++)
#pragma unroll
            for (int d = 0; d < 4; d++) c[a][b][d] = 0.0f;

    const int row0 = blockIdx.y * 128, col0 = blockIdx.x * 128;
    gemm_mainloop32(g_O, w, 512, row0, col0, sm, c);

    const int lane = threadIdx.x & 31, warp = threadIdx.x >> 5;
    const int wy = warp >> 2, wx = warp & 3, g = lane >> 2, tig = lane & 3;
#pragma unroll
    for (int mt = 0; mt < 4; mt++)
#pragma unroll
        for (int nt = 0; nt < 4; nt++) {
            int r = row0 + wy * 64 + mt * 16 + g;
            int cc = col0 + wx * 32 + nt * 8 + tig * 2;
            float b0 = bias[cc], b1 = bias[cc + 1];
            *(float2*)&out[(size_t)r * 512 + cc] =
                make_float2(c[mt][nt][0] + b0, c[mt][nt][1] + b1);
            *(float2*)&out[(size_t)(r + 8) * 512 + cc] =
                make_float2(c[mt][nt][2] + b0, c[mt][nt][3] + b1);
        }
}

// ---------------------------------------------------------------------------
extern "C" void kernel_launch(void* const* d_in, const int* in_sizes, int n_in,
                              void* d_out, int out_size) {
    const float* x     = (const float*)d_in[0];
    const float* w_qkv = (const float*)d_in[1];
    const float* w_out = (const float*)d_in[2];
    const float* b_out = (const float*)d_in[3];
    float* out = (float*)d_out;

    const int gemm_smem = 4 * 128 * 72 * 2;                 // 73728 B
    const int attn_smem = 4 * 128 * 72 * 2 + 128 * 72 * 2;  // 92160 B
    cudaFuncSetAttribute(qkv_gemm_mma, cudaFuncAttributeMaxDynamicSharedMemorySize, gemm_smem);
    cudaFuncSetAttribute(attn_mma, cudaFuncAttributeMaxDynamicSharedMemorySize, attn_smem);
    cudaFuncSetAttribute(out_gemm_mma, cudaFuncAttributeMaxDynamicSharedMemorySize, gemm_smem);

    qkv_gemm_mma<<<dim3(12, 64), 256, gemm_smem>>>(x, w_qkv);
    attn_mma<<<dim3(8, 64), 256, attn_smem>>>();
    out_gemm_mma<<<dim3(4, 64), 256, gemm_smem>>>(w_out, b_out, out);
}

// round 8
// speedup vs baseline: 2.4037x; 1.0333x over previous
#include <cuda_runtime.h>
#include <cuda_bf16.h>
#include <cuda_fp16.h>
#include <math.h>
#include <stdint.h>

// ---------------------------------------------------------------------------
// x(8192,512) @ w_qkv(512,1536) -> 64-head attention (n=1024, dh=64,
// scale=8^-0.5) -> @ w_out(512,512) + b_out. fp32 in/out, rel_err < 1e-3.
// Round 8: prepass fp32->bf16 hi/lo conversion (once), cp.async double-buffered
// mma mainloops everywhere. Device globals referenced ONLY from device code.
// ---------------------------------------------------------------------------

__device__ alignas(16) __nv_bfloat16 g_xh[8192 * 512], g_xl[8192 * 512];      // [m][k]
__device__ alignas(16) __nv_bfloat16 g_wqh[1536 * 512], g_wql[1536 * 512];    // [n][k] (transposed)
__device__ alignas(16) __nv_bfloat16 g_woh[512 * 512], g_wol[512 * 512];      // [n][k] (transposed)
__device__ alignas(16) __nv_bfloat16 g_Qh[64 * 1024 * 64], g_Ql[64 * 1024 * 64]; // [bh][n][d], pre-scaled
__device__ alignas(16) __nv_bfloat16 g_Kh[64 * 1024 * 64], g_Kl[64 * 1024 * 64]; // [bh][n][d]
__device__ alignas(16) __half        g_Vf[64 * 1024 * 64];                       // [bh][n][d]
__device__ alignas(16) __nv_bfloat16 g_Oh[8192 * 512], g_Ol[8192 * 512];         // [b*n][h*64+d]

// ---------------------------------------------------------------------------
__device__ __forceinline__ float fast_exp(float x) {
    float y = x * 1.4426950408889634f;
    y = fmaxf(y, -126.0f);
    y = fminf(y, 126.0f);
    float nf = rintf(y);
    float t = (y - nf) * 0.6931471805599453f;
    float p = 8.3333337e-3f;
    p = fmaf(p, t, 4.1666668e-2f);
    p = fmaf(p, t, 0.16666667f);
    p = fmaf(p, t, 0.5f);
    p = fmaf(p, t, 1.0f);
    p = fmaf(p, t, 1.0f);
    return p * __int_as_float(((int)nf + 127) << 23);
}

// ---------------------------------------------------------------------------
// primitives
__device__ __forceinline__ void ldsm4(uint32_t r[4], const void* p) {
    uint32_t a = (uint32_t)__cvta_generic_to_shared(p);
    asm volatile("ldmatrix.sync.aligned.m8n8.x4.shared.b16 {%0,%1,%2,%3}, [%4];"
                 : "=r"(r[0]), "=r"(r[1]), "=r"(r[2]), "=r"(r[3]) : "r"(a));
}
__device__ __forceinline__ void ldsm4t(uint32_t r[4], const void* p) {
    uint32_t a = (uint32_t)__cvta_generic_to_shared(p);
    asm volatile("ldmatrix.sync.aligned.m8n8.x4.trans.shared.b16 {%0,%1,%2,%3}, [%4];"
                 : "=r"(r[0]), "=r"(r[1]), "=r"(r[2]), "=r"(r[3]) : "r"(a));
}
__device__ __forceinline__ void mma_bf16(float c[4], const uint32_t a[4],
                                         uint32_t b0, uint32_t b1) {
    asm volatile(
        "mma.sync.aligned.m16n8k16.row.col.f32.bf16.bf16.f32 "
        "{%0,%1,%2,%3}, {%4,%5,%6,%7}, {%8,%9}, {%0,%1,%2,%3};"
        : "+f"(c[0]), "+f"(c[1]), "+f"(c[2]), "+f"(c[3])
        : "r"(a[0]), "r"(a[1]), "r"(a[2]), "r"(a[3]), "r"(b0), "r"(b1));
}
__device__ __forceinline__ void mma_f16(float c[4], const uint32_t a[4],
                                        uint32_t b0, uint32_t b1) {
    asm volatile(
        "mma.sync.aligned.m16n8k16.row.col.f32.f16.f16.f32 "
        "{%0,%1,%2,%3}, {%4,%5,%6,%7}, {%8,%9}, {%0,%1,%2,%3};"
        : "+f"(c[0]), "+f"(c[1]), "+f"(c[2]), "+f"(c[3])
        : "r"(a[0]), "r"(a[1]), "r"(a[2]), "r"(a[3]), "r"(b0), "r"(b1));
}
__device__ __forceinline__ uint32_t pack_half2(float lo, float hi) {
    __half2 h = __floats2half2_rn(lo, hi);
    return *reinterpret_cast<uint32_t*>(&h);
}
__device__ __forceinline__ void cp16(void* s, const void* g) {
    uint32_t a = (uint32_t)__cvta_generic_to_shared(s);
    asm volatile("cp.async.cg.shared.global [%0], [%1], 16;" :: "r"(a), "l"(g));
}
__device__ __forceinline__ void cp_commit() {
    asm volatile("cp.async.commit_group;");
}

// ---------------------------------------------------------------------------
// Prepass 1: split x -> g_xh/g_xl (writes symbols from device code)
__global__ __launch_bounds__(256) void prep_x(const float* __restrict__ x) {
    int i = blockIdx.x * 256 + threadIdx.x;          // one float4 per thread
    float4 v = *(const float4*)&x[(size_t)i * 4];
    alignas(8) __nv_bfloat16 hh[4], ll[4];
    float vv[4] = {v.x, v.y, v.z, v.w};
#pragma unroll
    for (int k = 0; k < 4; k++) {
        hh[k] = __float2bfloat16(vv[k]);
        ll[k] = __float2bfloat16(vv[k] - __bfloat162float(hh[k]));
    }
    *(uint2*)&g_xh[(size_t)i * 4] = *(const uint2*)hh;
    *(uint2*)&g_xl[(size_t)i * 4] = *(const uint2*)ll;
}

// Prepass 2: transpose W[k][n] -> T[n][k] hi/lo. which: 0 = w_qkv, 1 = w_out.
__global__ __launch_bounds__(256) void prep_w(const float* __restrict__ W,
                                              int ncols, int which) {
    __shared__ float tile[32][33];
    const int c0 = blockIdx.x * 32, r0 = blockIdx.y * 32;
    const int tx = threadIdx.x & 31, ty = threadIdx.x >> 5;
#pragma unroll
    for (int i = ty; i < 32; i += 8)
        tile[i][tx] = W[(size_t)(r0 + i) * ncols + c0 + tx];
    __syncthreads();
    __nv_bfloat16* Th = which ? g_woh : g_wqh;
    __nv_bfloat16* Tl = which ? g_wol : g_wql;
#pragma unroll
    for (int i = ty; i < 32; i += 8) {
        float v = tile[tx][i];   // = W[r0+tx][c0+i]
        __nv_bfloat16 h = __float2bfloat16(v);
        size_t o = (size_t)(c0 + i) * 512 + r0 + tx;
        Th[o] = h;
        Tl[o] = __float2bfloat16(v - __bfloat162float(h));
    }
}

// ---------------------------------------------------------------------------
// Shared 128x128 bf16x3 mainloop, K=512, chunk 64, cp.async 2-stage pipeline.
// A/B: bf16 [.][512] K-major hi/lo. Smem: 2 stages x 4 x [128][72] = 147456 B.
__device__ __forceinline__ void gemm_loop_bf16(
    const __nv_bfloat16* __restrict__ Ah, const __nv_bfloat16* __restrict__ Al,
    const __nv_bfloat16* __restrict__ Bh, const __nv_bfloat16* __restrict__ Bl,
    int row0, int col0, char* sm, float c[4][4][4]) {
    const int tid = threadIdx.x, lane = tid & 31, warp = tid >> 5;
    const int wy = warp >> 2, wx = warp & 3;
    const int lr = lane & 15, lc = (lane >> 4) * 8;
    const int STAGE = 4 * 128 * 72 * 2;   // 73728 B

#define LOAD_STAGE(kc, s)                                                         \
    {                                                                             \
        __nv_bfloat16* dAh = (__nv_bfloat16*)(sm + (s) * STAGE);                  \
        __nv_bfloat16* dAl = dAh + 128 * 72;                                      \
        __nv_bfloat16* dBh = dAl + 128 * 72;                                      \
        __nv_bfloat16* dBl = dBh + 128 * 72;                                      \
        _Pragma("unroll") for (int i = 0; i < 4; i++) {                           \
            int idx = i * 256 + tid;                                              \
            int r = idx >> 3, c8 = (idx & 7) * 8;                                 \
            cp16(&dAh[r * 72 + c8], &Ah[(size_t)(row0 + r) * 512 + (kc) + c8]);   \
            cp16(&dAl[r * 72 + c8], &Al[(size_t)(row0 + r) * 512 + (kc) + c8]);   \
            cp16(&dBh[r * 72 + c8], &Bh[(size_t)(col0 + r) * 512 + (kc) + c8]);   \
            cp16(&dBl[r * 72 + c8], &Bl[(size_t)(col0 + r) * 512 + (kc) + c8]);   \
        }                                                                         \
        cp_commit();                                                              \
    }

    LOAD_STAGE(0, 0)
    for (int ks = 0; ks < 8; ks++) {
        if (ks < 7) {
            LOAD_STAGE((ks + 1) * 64, (ks + 1) & 1)
            asm volatile("cp.async.wait_group 1;");
        } else {
            asm volatile("cp.async.wait_group 0;");
        }
        __syncthreads();
        __nv_bfloat16* sAh = (__nv_bfloat16*)(sm + (ks & 1) * STAGE);
        __nv_bfloat16* sAl = sAh + 128 * 72;
        __nv_bfloat16* sBh = sAl + 128 * 72;
        __nv_bfloat16* sBl = sBh + 128 * 72;
#pragma unroll
        for (int kt = 0; kt < 4; kt++) {
            uint32_t ah[4][4], al[4][4];
#pragma unroll
            for (int mt = 0; mt < 4; mt++) {
                int ro = (wy * 64 + mt * 16 + lr) * 72 + kt * 16 + lc;
                ldsm4(ah[mt], &sAh[ro]);
                ldsm4(al[mt], &sAl[ro]);
            }
#pragma unroll
            for (int nt16 = 0; nt16 < 2; nt16++) {
                uint32_t bh[4], bl[4];
                int ro = (wx * 32 + nt16 * 16 + lr) * 72 + kt * 16 + lc;
                ldsm4(bh, &sBh[ro]);
                ldsm4(bl, &sBl[ro]);
#pragma unroll
                for (int mt = 0; mt < 4; mt++) {
                    float* c0 = c[mt][nt16 * 2];
                    float* c1 = c[mt][nt16 * 2 + 1];
                    mma_bf16(c0, ah[mt], bh[0], bh[2]);
                    mma_bf16(c0, ah[mt], bl[0], bl[2]);
                    mma_bf16(c0, al[mt], bh[0], bh[2]);
                    mma_bf16(c1, ah[mt], bh[1], bh[3]);
                    mma_bf16(c1, ah[mt], bl[1], bl[3]);
                    mma_bf16(c1, al[mt], bh[1], bh[3]);
                }
            }
        }
        __syncthreads();
    }
#undef LOAD_STAGE
}

// ---------------------------------------------------------------------------
// Kernel 1: QKV projection -> Q/K bf16 hi/lo [bh][n][d] (Q pre-scaled), V fp16
__global__ __launch_bounds__(256) void qkv_gemm_mma() {
    extern __shared__ char sm[];
    float c[4][4][4];
#pragma unroll
    for (int a = 0; a < 4; a++)
#pragma unroll
        for (int b = 0; b < 4; b++)
#pragma unroll
            for (int d = 0; d < 4; d++) c[a][b][d] = 0.0f;

    const int row0 = blockIdx.y * 128, col0 = blockIdx.x * 128;
    gemm_loop_bf16(g_xh, g_xl, g_wqh, g_wql, row0, col0, sm, c);

    float* Cs = (float*)sm;
    __syncthreads();
    const int lane = threadIdx.x & 31, warp = threadIdx.x >> 5;
    const int wy = warp >> 2, wx = warp & 3, g = lane >> 2, tig = lane & 3;
#pragma unroll
    for (int mt = 0; mt < 4; mt++)
#pragma unroll
        for (int nt = 0; nt < 4; nt++) {
            int r = wy * 64 + mt * 16 + g, cc = wx * 32 + nt * 8 + tig * 2;
            Cs[r * 132 + cc] = c[mt][nt][0];
            Cs[r * 132 + cc + 1] = c[mt][nt][1];
            Cs[(r + 8) * 132 + cc] = c[mt][nt][2];
            Cs[(r + 8) * 132 + cc + 1] = c[mt][nt][3];
        }
    __syncthreads();

    const int tid = threadIdx.x;
    const int ty = tid >> 4, tx = tid & 15;
    const int jloc = tx * 8, j0 = col0 + jloc;
    const int h = j0 / 192, part = (j0 % 192) >> 6, d0 = j0 & 63;
    const int rowg0 = row0 + ty * 8;
    const int b_idx = rowg0 >> 10, n0 = rowg0 & 1023, bh = b_idx * 8 + h;
    const float qs = 0.35355339059327373f;   // 8^-0.5 (batch-size scale!)

#pragma unroll
    for (int r = 0; r < 8; r++) {
        float v[8];
#pragma unroll
        for (int k = 0; k < 8; k++) v[k] = Cs[(ty * 8 + r) * 132 + jloc + k];
        size_t base = ((size_t)bh * 1024 + n0 + r) * 64 + d0;
        if (part == 0) {
            alignas(16) __nv_bfloat16 hh[8], ll[8];
#pragma unroll
            for (int k = 0; k < 8; k++) {
                float sv = v[k] * qs;
                hh[k] = __float2bfloat16(sv);
                ll[k] = __float2bfloat16(sv - __bfloat162float(hh[k]));
            }
            *(uint4*)&g_Qh[base] = *(const uint4*)hh;
            *(uint4*)&g_Ql[base] = *(const uint4*)ll;
        } else if (part == 1) {
            alignas(16) __nv_bfloat16 hh[8], ll[8];
#pragma unroll
            for (int k = 0; k < 8; k++) {
                hh[k] = __float2bfloat16(v[k]);
                ll[k] = __float2bfloat16(v[k] - __bfloat162float(hh[k]));
            }
            *(uint4*)&g_Kh[base] = *(const uint4*)hh;
            *(uint4*)&g_Kl[base] = *(const uint4*)ll;
        } else {
            alignas(16) __half hv[8];
#pragma unroll
            for (int k = 0; k < 8; k++) hv[k] = __float2half_rn(v[k]);
            *(uint4*)&g_Vf[base] = *(const uint4*)hv;
        }
    }
}

// ---------------------------------------------------------------------------
// Kernel 2: fused flash attention, cp.async double-buffered K/V.
// smem: Qh,Ql [128][72] + 2 stages x (Kh,Kl,V) = 36864 + 2*55296 = 147456 B.
__global__ __launch_bounds__(256) void attn_mma() {
    extern __shared__ char sm[];
    const int QBYTES = 2 * 128 * 72 * 2;      // 36864
    const int KVSTAGE = 3 * 128 * 72 * 2;     // 55296
    __nv_bfloat16* sQh = (__nv_bfloat16*)sm;
    __nv_bfloat16* sQl = sQh + 128 * 72;

    const int tid = threadIdx.x, lane = tid & 31, warp = tid >> 5;
    const int g = lane >> 2, tig = lane & 3;
    const int lr = lane & 15, lc = (lane >> 4) * 8;
    const int vrow = ((lane >> 3) & 1) * 8 + (lane & 7);
    const int vcol = (lane >> 4) * 8;

    const int bh = blockIdx.y;
    const int i0 = blockIdx.x * 128;
    const size_t hb = (size_t)bh * 1024 * 64;

#define LOAD_KV(j0, s)                                                            \
    {                                                                             \
        char* b = sm + QBYTES + (s) * KVSTAGE;                                    \
        __nv_bfloat16* dKh = (__nv_bfloat16*)b;                                   \
        __nv_bfloat16* dKl = dKh + 128 * 72;                                      \
        __half* dV = (__half*)(dKl + 128 * 72);                                   \
        _Pragma("unroll") for (int i = 0; i < 4; i++) {                           \
            int idx = i * 256 + tid;                                              \
            int r = idx >> 3, c8 = (idx & 7) * 8;                                 \
            cp16(&dKh[r * 72 + c8], &g_Kh[hb + (size_t)((j0) + r) * 64 + c8]);    \
            cp16(&dKl[r * 72 + c8], &g_Kl[hb + (size_t)((j0) + r) * 64 + c8]);    \
            cp16(&dV[r * 72 + c8],  &g_Vf[hb + (size_t)((j0) + r) * 64 + c8]);    \
        }                                                                         \
        cp_commit();                                                              \
    }

    // Q tile copies join stage-0's commit group
#pragma unroll
    for (int i = 0; i < 4; i++) {
        int idx = i * 256 + tid;
        int r = idx >> 3, c8 = (idx & 7) * 8;
        cp16(&sQh[r * 72 + c8], &g_Qh[hb + (size_t)(i0 + r) * 64 + c8]);
        cp16(&sQl[r * 72 + c8], &g_Ql[hb + (size_t)(i0 + r) * 64 + c8]);
    }
    LOAD_KV(0, 0)

    float o[8][4];
#pragma unroll
    for (int d = 0; d < 8; d++)
#pragma unroll
        for (int k = 0; k < 4; k++) o[d][k] = 0.0f;
    float m0 = -1e30f, m1 = -1e30f, l0 = 0.0f, l1 = 0.0f;

    for (int jt = 0; jt < 8; jt++) {
        if (jt < 7) {
            LOAD_KV((jt + 1) * 128, (jt + 1) & 1)
            asm volatile("cp.async.wait_group 1;");
        } else {
            asm volatile("cp.async.wait_group 0;");
        }
        __syncthreads();
        char* b = sm + QBYTES + (jt & 1) * KVSTAGE;
        __nv_bfloat16* sKh = (__nv_bfloat16*)b;
        __nv_bfloat16* sKl = sKh + 128 * 72;
        __half* sV = (__half*)(sKl + 128 * 72);

        // S = Q K^T over d=64; warp rows warp*16..+15; 16 n8 tiles
        float s[16][4];
#pragma unroll
        for (int t = 0; t < 16; t++)
#pragma unroll
            for (int k = 0; k < 4; k++) s[t][k] = 0.0f;

#pragma unroll
        for (int kt = 0; kt < 4; kt++) {
            uint32_t qh[4], ql[4];
            int qo = (warp * 16 + lr) * 72 + kt * 16 + lc;
            ldsm4(qh, &sQh[qo]);
            ldsm4(ql, &sQl[qo]);
#pragma unroll
            for (int nt = 0; nt < 8; nt++) {
                uint32_t kh[4], kl[4];
                int ko = (nt * 16 + lr) * 72 + kt * 16 + lc;
                ldsm4(kh, &sKh[ko]);
                ldsm4(kl, &sKl[ko]);
                float* s0 = s[nt * 2];
                float* s1 = s[nt * 2 + 1];
                mma_bf16(s0, qh, kh[0], kh[2]);
                mma_bf16(s0, qh, kl[0], kl[2]);
                mma_bf16(s0, ql, kh[0], kh[2]);
                mma_bf16(s1, qh, kh[1], kh[3]);
                mma_bf16(s1, qh, kl[1], kl[3]);
                mma_bf16(s1, ql, kh[1], kh[3]);
            }
        }

        // Online softmax (rows g / g+8, 4 tig lanes per row)
        float rmax0 = -1e30f, rmax1 = -1e30f;
#pragma unroll
        for (int t = 0; t < 16; t++) {
            rmax0 = fmaxf(rmax0, fmaxf(s[t][0], s[t][1]));
            rmax1 = fmaxf(rmax1, fmaxf(s[t][2], s[t][3]));
        }
        rmax0 = fmaxf(rmax0, __shfl_xor_sync(0xffffffffu, rmax0, 1));
        rmax0 = fmaxf(rmax0, __shfl_xor_sync(0xffffffffu, rmax0, 2));
        rmax1 = fmaxf(rmax1, __shfl_xor_sync(0xffffffffu, rmax1, 1));
        rmax1 = fmaxf(rmax1, __shfl_xor_sync(0xffffffffu, rmax1, 2));
        float mn0 = fmaxf(m0, rmax0), mn1 = fmaxf(m1, rmax1);
        float cr0 = fast_exp(m0 - mn0), cr1 = fast_exp(m1 - mn1);
        float sum0 = 0.0f, sum1 = 0.0f;
#pragma unroll
        for (int t = 0; t < 16; t++) {
            s[t][0] = fast_exp(s[t][0] - mn0);
            s[t][1] = fast_exp(s[t][1] - mn0);
            s[t][2] = fast_exp(s[t][2] - mn1);
            s[t][3] = fast_exp(s[t][3] - mn1);
            sum0 += s[t][0] + s[t][1];
            sum1 += s[t][2] + s[t][3];
        }
        sum0 += __shfl_xor_sync(0xffffffffu, sum0, 1);
        sum0 += __shfl_xor_sync(0xffffffffu, sum0, 2);
        sum1 += __shfl_xor_sync(0xffffffffu, sum1, 1);
        sum1 += __shfl_xor_sync(0xffffffffu, sum1, 2);
        l0 = l0 * cr0 + sum0;
        l1 = l1 * cr1 + sum1;
        m0 = mn0;
        m1 = mn1;
#pragma unroll
        for (int d = 0; d < 8; d++) {
            o[d][0] *= cr0; o[d][1] *= cr0;
            o[d][2] *= cr1; o[d][3] *= cr1;
        }

        // O += P V  (P C-frag -> fp16 A-frag; V via ldmatrix.trans)
#pragma unroll
        for (int jt16 = 0; jt16 < 8; jt16++) {
            uint32_t a[4];
            a[0] = pack_half2(s[jt16 * 2][0], s[jt16 * 2][1]);
            a[1] = pack_half2(s[jt16 * 2][2], s[jt16 * 2][3]);
            a[2] = pack_half2(s[jt16 * 2 + 1][0], s[jt16 * 2 + 1][1]);
            a[3] = pack_half2(s[jt16 * 2 + 1][2], s[jt16 * 2 + 1][3]);
#pragma unroll
            for (int dt16 = 0; dt16 < 4; dt16++) {
                uint32_t v[4];
                ldsm4t(v, &sV[(jt16 * 16 + vrow) * 72 + dt16 * 16 + vcol]);
                mma_f16(o[dt16 * 2], a, v[0], v[1]);
                mma_f16(o[dt16 * 2 + 1], a, v[2], v[3]);
            }
        }
        __syncthreads();
    }
#undef LOAD_KV

    // Epilogue: normalize, split to bf16 hi/lo, write [b*n][h*64+d]
    const float inv0 = 1.0f / l0, inv1 = 1.0f / l1;
    const int b_idx = bh >> 3, h = bh & 7;
    const size_t rowa = (size_t)b_idx * 1024 + i0 + warp * 16 + g;
    const size_t rowb = rowa + 8;
    const int colb = h * 64 + tig * 2;
#pragma unroll
    for (int dt = 0; dt < 8; dt++) {
        int col = colb + dt * 8;
        float v0 = o[dt][0] * inv0, v1 = o[dt][1] * inv0;
        float v2 = o[dt][2] * inv1, v3 = o[dt][3] * inv1;
        __nv_bfloat162 ph, pl;
        ph.x = __float2bfloat16(v0); ph.y = __float2bfloat16(v1);
        pl.x = __float2bfloat16(v0 - __bfloat162float(ph.x));
        pl.y = __float2bfloat16(v1 - __bfloat162float(ph.y));
        *(__nv_bfloat162*)&g_Oh[rowa * 512 + col] = ph;
        *(__nv_bfloat162*)&g_Ol[rowa * 512 + col] = pl;
        ph.x = __float2bfloat16(v2); ph.y = __float2bfloat16(v3);
        pl.x = __float2bfloat16(v2 - __bfloat162float(ph.x));
        pl.y = __float2bfloat16(v3 - __bfloat162float(ph.y));
        *(__nv_bfloat162*)&g_Oh[rowb * 512 + col] = ph;
        *(__nv_bfloat162*)&g_Ol[rowb * 512 + col] = pl;
    }
}

// ---------------------------------------------------------------------------
// Kernel 3: output projection out = O @ w_out + b_out
__global__ __launch_bounds__(256) void out_gemm_mma(const float* __restrict__ bias,
                                                    float* __restrict__ out) {
    extern __shared__ char sm[];
    float c[4][4][4];
#pragma unroll
    for (int a = 0; a < 4; a++)
#pragma unroll
        for (int b = 0; b < 4; b++)
#pragma unroll
            for (int d = 0; d < 4; d++) c[a][b][d] = 0.0f;

    const int row0 = blockIdx.y * 128, col0 = blockIdx.x * 128;
    gemm_loop_bf16(g_Oh, g_Ol, g_woh, g_wol, row0, col0, sm, c);

    const int lane = threadIdx.x & 31, warp = threadIdx.x >> 5;
    const int wy = warp >> 2, wx = warp & 3, g = lane >> 2, tig = lane & 3;
#pragma unroll
    for (int mt = 0; mt < 4; mt++)
#pragma unroll
        for (int nt = 0; nt < 4; nt++) {
            int r = row0 + wy * 64 + mt * 16 + g;
            int cc = col0 + wx * 32 + nt * 8 + tig * 2;
            float b0 = bias[cc], b1 = bias[cc + 1];
            *(float2*)&out[(size_t)r * 512 + cc] =
                make_float2(c[mt][nt][0] + b0, c[mt][nt][1] + b1);
            *(float2*)&out[(size_t)(r + 8) * 512 + cc] =
                make_float2(c[mt][nt][2] + b0, c[mt][nt][3] + b1);
        }
}

// ---------------------------------------------------------------------------
extern "C" void kernel_launch(void* const* d_in, const int* in_sizes, int n_in,
                              void* d_out, int out_size) {
    const float* x     = (const float*)d_in[0];
    const float* w_qkv = (const float*)d_in[1];
    const float* w_out = (const float*)d_in[2];
    const float* b_out = (const float*)d_in[3];
    float* out = (float*)d_out;

    const int pipe_smem = 2 * 4 * 128 * 72 * 2;   // 147456 B (covers Cs 67584)
    cudaFuncSetAttribute(qkv_gemm_mma, cudaFuncAttributeMaxDynamicSharedMemorySize, pipe_smem);
    cudaFuncSetAttribute(attn_mma, cudaFuncAttributeMaxDynamicSharedMemorySize, pipe_smem);
    cudaFuncSetAttribute(out_gemm_mma, cudaFuncAttributeMaxDynamicSharedMemorySize, pipe_smem);

    prep_x<<<4096, 256>>>(x);                      // 8192*512/4 threads
    prep_w<<<dim3(48, 16), 256>>>(w_qkv, 1536, 0);
    prep_w<<<dim3(16, 16), 256>>>(w_out, 512, 1);
    qkv_gemm_mma<<<dim3(12, 64), 256, pipe_smem>>>();
    attn_mma<<<dim3(8, 64), 256, pipe_smem>>>();
    out_gemm_mma<<<dim3(4, 64), 256, pipe_smem>>>(b_out, out);
}

// round 9
// speedup vs baseline: 2.6476x; 1.1015x over previous
#include <cuda_runtime.h>
#include <cuda_bf16.h>
#include <cuda_fp16.h>
#include <math.h>
#include <stdint.h>

// ---------------------------------------------------------------------------
// x(8192,512) @ w_qkv(512,1536) -> 64-head attention (n=1024, dh=64,
// scale=8^-0.5) -> @ w_out(512,512) + b_out. fp32 in/out, rel_err < 1e-3.
// Round 9: 2 CTAs/SM everywhere (smem <= 92KB/CTA), k-chunk 32 double-buffered
// GEMMs, single-buffer K/V attention with cross-CTA overlap.
// ---------------------------------------------------------------------------

__device__ alignas(16) __nv_bfloat16 g_xh[8192 * 512], g_xl[8192 * 512];      // [m][k]
__device__ alignas(16) __nv_bfloat16 g_wqh[1536 * 512], g_wql[1536 * 512];    // [n][k]
__device__ alignas(16) __nv_bfloat16 g_woh[512 * 512], g_wol[512 * 512];      // [n][k]
__device__ alignas(16) __nv_bfloat16 g_Qh[64 * 1024 * 64], g_Ql[64 * 1024 * 64]; // [bh][n][d]
__device__ alignas(16) __nv_bfloat16 g_Kh[64 * 1024 * 64], g_Kl[64 * 1024 * 64]; // [bh][n][d]
__device__ alignas(16) __half        g_Vf[64 * 1024 * 64];                       // [bh][n][d]
__device__ alignas(16) __nv_bfloat16 g_Oh[8192 * 512], g_Ol[8192 * 512];         // [b*n][h*64+d]

// ---------------------------------------------------------------------------
__device__ __forceinline__ float fast_exp(float x) {
    float y = x * 1.4426950408889634f;
    y = fmaxf(y, -126.0f);
    y = fminf(y, 126.0f);
    float nf = rintf(y);
    float t = (y - nf) * 0.6931471805599453f;
    float p = 8.3333337e-3f;
    p = fmaf(p, t, 4.1666668e-2f);
    p = fmaf(p, t, 0.16666667f);
    p = fmaf(p, t, 0.5f);
    p = fmaf(p, t, 1.0f);
    p = fmaf(p, t, 1.0f);
    return p * __int_as_float(((int)nf + 127) << 23);
}

// ---------------------------------------------------------------------------
__device__ __forceinline__ void ldsm4(uint32_t r[4], const void* p) {
    uint32_t a = (uint32_t)__cvta_generic_to_shared(p);
    asm volatile("ldmatrix.sync.aligned.m8n8.x4.shared.b16 {%0,%1,%2,%3}, [%4];"
                 : "=r"(r[0]), "=r"(r[1]), "=r"(r[2]), "=r"(r[3]) : "r"(a));
}
__device__ __forceinline__ void ldsm4t(uint32_t r[4], const void* p) {
    uint32_t a = (uint32_t)__cvta_generic_to_shared(p);
    asm volatile("ldmatrix.sync.aligned.m8n8.x4.trans.shared.b16 {%0,%1,%2,%3}, [%4];"
                 : "=r"(r[0]), "=r"(r[1]), "=r"(r[2]), "=r"(r[3]) : "r"(a));
}
__device__ __forceinline__ void mma_bf16(float c[4], const uint32_t a[4],
                                         uint32_t b0, uint32_t b1) {
    asm volatile(
        "mma.sync.aligned.m16n8k16.row.col.f32.bf16.bf16.f32 "
        "{%0,%1,%2,%3}, {%4,%5,%6,%7}, {%8,%9}, {%0,%1,%2,%3};"
        : "+f"(c[0]), "+f"(c[1]), "+f"(c[2]), "+f"(c[3])
        : "r"(a[0]), "r"(a[1]), "r"(a[2]), "r"(a[3]), "r"(b0), "r"(b1));
}
__device__ __forceinline__ void mma_f16(float c[4], const uint32_t a[4],
                                        uint32_t b0, uint32_t b1) {
    asm volatile(
        "mma.sync.aligned.m16n8k16.row.col.f32.f16.f16.f32 "
        "{%0,%1,%2,%3}, {%4,%5,%6,%7}, {%8,%9}, {%0,%1,%2,%3};"
        : "+f"(c[0]), "+f"(c[1]), "+f"(c[2]), "+f"(c[3])
        : "r"(a[0]), "r"(a[1]), "r"(a[2]), "r"(a[3]), "r"(b0), "r"(b1));
}
__device__ __forceinline__ uint32_t pack_half2(float lo, float hi) {
    __half2 h = __floats2half2_rn(lo, hi);
    return *reinterpret_cast<uint32_t*>(&h);
}
__device__ __forceinline__ void cp16(void* s, const void* g) {
    uint32_t a = (uint32_t)__cvta_generic_to_shared(s);
    asm volatile("cp.async.cg.shared.global [%0], [%1], 16;" :: "r"(a), "l"(g));
}
__device__ __forceinline__ void cp_commit() {
    asm volatile("cp.async.commit_group;");
}

// ---------------------------------------------------------------------------
// Prepasses (device-symbol writes happen in device code only)
__global__ __launch_bounds__(256) void prep_x(const float* __restrict__ x) {
    int i = blockIdx.x * 256 + threadIdx.x;
    float4 v = *(const float4*)&x[(size_t)i * 4];
    alignas(8) __nv_bfloat16 hh[4], ll[4];
    float vv[4] = {v.x, v.y, v.z, v.w};
#pragma unroll
    for (int k = 0; k < 4; k++) {
        hh[k] = __float2bfloat16(vv[k]);
        ll[k] = __float2bfloat16(vv[k] - __bfloat162float(hh[k]));
    }
    *(uint2*)&g_xh[(size_t)i * 4] = *(const uint2*)hh;
    *(uint2*)&g_xl[(size_t)i * 4] = *(const uint2*)ll;
}

__global__ __launch_bounds__(256) void prep_w(const float* __restrict__ W,
                                              int ncols, int which) {
    __shared__ float tile[32][33];
    const int c0 = blockIdx.x * 32, r0 = blockIdx.y * 32;
    const int tx = threadIdx.x & 31, ty = threadIdx.x >> 5;
#pragma unroll
    for (int i = ty; i < 32; i += 8)
        tile[i][tx] = W[(size_t)(r0 + i) * ncols + c0 + tx];
    __syncthreads();
    __nv_bfloat16* Th = which ? g_woh : g_wqh;
    __nv_bfloat16* Tl = which ? g_wol : g_wql;
#pragma unroll
    for (int i = ty; i < 32; i += 8) {
        float v = tile[tx][i];
        __nv_bfloat16 h = __float2bfloat16(v);
        size_t o = (size_t)(c0 + i) * 512 + r0 + tx;
        Th[o] = h;
        Tl[o] = __float2bfloat16(v - __bfloat162float(h));
    }
}

// ---------------------------------------------------------------------------
// 128x128 bf16x3 mainloop. K=512, chunk 32, 2-stage cp.async, 2 CTAs/SM.
// Smem layout [128][40] bf16 per matrix (80B rows: ldmatrix conflict-free).
// Stage = 4*128*40*2 = 40960 B; 2 stages = 81920 B.
__device__ __forceinline__ void gemm_loop_bf16(
    const __nv_bfloat16* __restrict__ Ah, const __nv_bfloat16* __restrict__ Al,
    const __nv_bfloat16* __restrict__ Bh, const __nv_bfloat16* __restrict__ Bl,
    int row0, int col0, char* sm, float c[4][4][4]) {
    const int tid = threadIdx.x, lane = tid & 31, warp = tid >> 5;
    const int wy = warp >> 2, wx = warp & 3;
    const int lr = lane & 15, lc = (lane >> 4) * 8;
    const int STAGE = 4 * 128 * 40 * 2;   // 40960 B

#define LOAD_STAGE(kc, s)                                                         \
    {                                                                             \
        __nv_bfloat16* dAh = (__nv_bfloat16*)(sm + (s) * STAGE);                  \
        __nv_bfloat16* dAl = dAh + 128 * 40;                                      \
        __nv_bfloat16* dBh = dAl + 128 * 40;                                      \
        __nv_bfloat16* dBl = dBh + 128 * 40;                                      \
        _Pragma("unroll") for (int i = 0; i < 2; i++) {                           \
            int idx = i * 256 + tid;                                              \
            int r = idx >> 2, c8 = (idx & 3) * 8;                                 \
            cp16(&dAh[r * 40 + c8], &Ah[(size_t)(row0 + r) * 512 + (kc) + c8]);   \
            cp16(&dAl[r * 40 + c8], &Al[(size_t)(row0 + r) * 512 + (kc) + c8]);   \
            cp16(&dBh[r * 40 + c8], &Bh[(size_t)(col0 + r) * 512 + (kc) + c8]);   \
            cp16(&dBl[r * 40 + c8], &Bl[(size_t)(col0 + r) * 512 + (kc) + c8]);   \
        }                                                                         \
        cp_commit();                                                              \
    }

    LOAD_STAGE(0, 0)
    for (int ks = 0; ks < 16; ks++) {
        if (ks < 15) {
            LOAD_STAGE((ks + 1) * 32, (ks + 1) & 1)
            asm volatile("cp.async.wait_group 1;");
        } else {
            asm volatile("cp.async.wait_group 0;");
        }
        __syncthreads();
        __nv_bfloat16* sAh = (__nv_bfloat16*)(sm + (ks & 1) * STAGE);
        __nv_bfloat16* sAl = sAh + 128 * 40;
        __nv_bfloat16* sBh = sAl + 128 * 40;
        __nv_bfloat16* sBl = sBh + 128 * 40;
#pragma unroll
        for (int kt = 0; kt < 2; kt++) {
            uint32_t ah[4][4], al[4][4];
#pragma unroll
            for (int mt = 0; mt < 4; mt++) {
                int ro = (wy * 64 + mt * 16 + lr) * 40 + kt * 16 + lc;
                ldsm4(ah[mt], &sAh[ro]);
                ldsm4(al[mt], &sAl[ro]);
            }
#pragma unroll
            for (int nt16 = 0; nt16 < 2; nt16++) {
                uint32_t bh[4], bl[4];
                int ro = (wx * 32 + nt16 * 16 + lr) * 40 + kt * 16 + lc;
                ldsm4(bh, &sBh[ro]);
                ldsm4(bl, &sBl[ro]);
#pragma unroll
                for (int mt = 0; mt < 4; mt++) {
                    float* c0 = c[mt][nt16 * 2];
                    float* c1 = c[mt][nt16 * 2 + 1];
                    mma_bf16(c0, ah[mt], bh[0], bh[2]);
                    mma_bf16(c0, ah[mt], bl[0], bl[2]);
                    mma_bf16(c0, al[mt], bh[0], bh[2]);
                    mma_bf16(c1, ah[mt], bh[1], bh[3]);
                    mma_bf16(c1, ah[mt], bl[1], bl[3]);
                    mma_bf16(c1, al[mt], bh[1], bh[3]);
                }
            }
        }
        __syncthreads();
    }
#undef LOAD_STAGE
}

// ---------------------------------------------------------------------------
// Kernel 1: QKV projection -> Q/K bf16 hi/lo [bh][n][d] (Q pre-scaled), V fp16
__global__ __launch_bounds__(256, 2) void qkv_gemm_mma() {
    extern __shared__ char sm[];
    float c[4][4][4];
#pragma unroll
    for (int a = 0; a < 4; a++)
#pragma unroll
        for (int b = 0; b < 4; b++)
#pragma unroll
            for (int d = 0; d < 4; d++) c[a][b][d] = 0.0f;

    const int row0 = blockIdx.y * 128, col0 = blockIdx.x * 128;
    gemm_loop_bf16(g_xh, g_xl, g_wqh, g_wql, row0, col0, sm, c);

    float* Cs = (float*)sm;
    __syncthreads();
    const int lane = threadIdx.x & 31, warp = threadIdx.x >> 5;
    const int wy = warp >> 2, wx = warp & 3, g = lane >> 2, tig = lane & 3;
#pragma unroll
    for (int mt = 0; mt < 4; mt++)
#pragma unroll
        for (int nt = 0; nt < 4; nt++) {
            int r = wy * 64 + mt * 16 + g, cc = wx * 32 + nt * 8 + tig * 2;
            Cs[r * 132 + cc] = c[mt][nt][0];
            Cs[r * 132 + cc + 1] = c[mt][nt][1];
            Cs[(r + 8) * 132 + cc] = c[mt][nt][2];
            Cs[(r + 8) * 132 + cc + 1] = c[mt][nt][3];
        }
    __syncthreads();

    const int tid = threadIdx.x;
    const int ty = tid >> 4, tx = tid & 15;
    const int jloc = tx * 8, j0 = col0 + jloc;
    const int h = j0 / 192, part = (j0 % 192) >> 6, d0 = j0 & 63;
    const int rowg0 = row0 + ty * 8;
    const int b_idx = rowg0 >> 10, n0 = rowg0 & 1023, bh = b_idx * 8 + h;
    const float qs = 0.35355339059327373f;   // 8^-0.5 (batch-size scale!)

#pragma unroll
    for (int r = 0; r < 8; r++) {
        float v[8];
#pragma unroll
        for (int k = 0; k < 8; k++) v[k] = Cs[(ty * 8 + r) * 132 + jloc + k];
        size_t base = ((size_t)bh * 1024 + n0 + r) * 64 + d0;
        if (part == 0) {
            alignas(16) __nv_bfloat16 hh[8], ll[8];
#pragma unroll
            for (int k = 0; k < 8; k++) {
                float sv = v[k] * qs;
                hh[k] = __float2bfloat16(sv);
                ll[k] = __float2bfloat16(sv - __bfloat162float(hh[k]));
            }
            *(uint4*)&g_Qh[base] = *(const uint4*)hh;
            *(uint4*)&g_Ql[base] = *(const uint4*)ll;
        } else if (part == 1) {
            alignas(16) __nv_bfloat16 hh[8], ll[8];
#pragma unroll
            for (int k = 0; k < 8; k++) {
                hh[k] = __float2bfloat16(v[k]);
                ll[k] = __float2bfloat16(v[k] - __bfloat162float(hh[k]));
            }
            *(uint4*)&g_Kh[base] = *(const uint4*)hh;
            *(uint4*)&g_Kl[base] = *(const uint4*)ll;
        } else {
            alignas(16) __half hv[8];
#pragma unroll
            for (int k = 0; k < 8; k++) hv[k] = __float2half_rn(v[k]);
            *(uint4*)&g_Vf[base] = *(const uint4*)hv;
        }
    }
}

// ---------------------------------------------------------------------------
// Kernel 2: fused flash attention, single K/V buffer, 2 CTAs/SM.
// smem: Qh,Ql + Kh,Kl,V  = 5 x 128*72*2 = 92160 B.
__global__ __launch_bounds__(256, 2) void attn_mma() {
    extern __shared__ char sm[];
    __nv_bfloat16* sQh = (__nv_bfloat16*)sm;
    __nv_bfloat16* sQl = sQh + 128 * 72;
    __nv_bfloat16* sKh = sQl + 128 * 72;
    __nv_bfloat16* sKl = sKh + 128 * 72;
    __half* sV = (__half*)(sKl + 128 * 72);

    const int tid = threadIdx.x, lane = tid & 31, warp = tid >> 5;
    const int g = lane >> 2, tig = lane & 3;
    const int lr = lane & 15, lc = (lane >> 4) * 8;
    const int vrow = ((lane >> 3) & 1) * 8 + (lane & 7);
    const int vcol = (lane >> 4) * 8;

    const int bh = blockIdx.y;
    const int i0 = blockIdx.x * 128;
    const size_t hb = (size_t)bh * 1024 * 64;

#define LOAD_KV(j0)                                                               \
    {                                                                             \
        _Pragma("unroll") for (int i = 0; i < 4; i++) {                           \
            int idx = i * 256 + tid;                                              \
            int r = idx >> 3, c8 = (idx & 7) * 8;                                 \
            cp16(&sKh[r * 72 + c8], &g_Kh[hb + (size_t)((j0) + r) * 64 + c8]);    \
            cp16(&sKl[r * 72 + c8], &g_Kl[hb + (size_t)((j0) + r) * 64 + c8]);    \
            cp16(&sV[r * 72 + c8],  &g_Vf[hb + (size_t)((j0) + r) * 64 + c8]);    \
        }                                                                         \
        cp_commit();                                                              \
    }

#pragma unroll
    for (int i = 0; i < 4; i++) {
        int idx = i * 256 + tid;
        int r = idx >> 3, c8 = (idx & 7) * 8;
        cp16(&sQh[r * 72 + c8], &g_Qh[hb + (size_t)(i0 + r) * 64 + c8]);
        cp16(&sQl[r * 72 + c8], &g_Ql[hb + (size_t)(i0 + r) * 64 + c8]);
    }
    LOAD_KV(0)
    asm volatile("cp.async.wait_group 0;");
    __syncthreads();

    float o[8][4];
#pragma unroll
    for (int d = 0; d < 8; d++)
#pragma unroll
        for (int k = 0; k < 4; k++) o[d][k] = 0.0f;
    float m0 = -1e30f, m1 = -1e30f, l0 = 0.0f, l1 = 0.0f;

    for (int jt = 0; jt < 8; jt++) {
        // S = Q K^T over d=64; warp rows warp*16..+15; 16 n8 tiles
        float s[16][4];
#pragma unroll
        for (int t = 0; t < 16; t++)
#pragma unroll
            for (int k = 0; k < 4; k++) s[t][k] = 0.0f;

#pragma unroll
        for (int kt = 0; kt < 4; kt++) {
            uint32_t qh[4], ql[4];
            int qo = (warp * 16 + lr) * 72 + kt * 16 + lc;
            ldsm4(qh, &sQh[qo]);
            ldsm4(ql, &sQl[qo]);
#pragma unroll
            for (int nt = 0; nt < 8; nt++) {
                uint32_t kh[4], kl[4];
                int ko = (nt * 16 + lr) * 72 + kt * 16 + lc;
                ldsm4(kh, &sKh[ko]);
                ldsm4(kl, &sKl[ko]);
                float* s0 = s[nt * 2];
                float* s1 = s[nt * 2 + 1];
                mma_bf16(s0, qh, kh[0], kh[2]);
                mma_bf16(s0, qh, kl[0], kl[2]);
                mma_bf16(s0, ql, kh[0], kh[2]);
                mma_bf16(s1, qh, kh[1], kh[3]);
                mma_bf16(s1, qh, kl[1], kl[3]);
                mma_bf16(s1, ql, kh[1], kh[3]);
            }
        }

        // Online softmax
        float rmax0 = -1e30f, rmax1 = -1e30f;
#pragma unroll
        for (int t = 0; t < 16; t++) {
            rmax0 = fmaxf(rmax0, fmaxf(s[t][0], s[t][1]));
            rmax1 = fmaxf(rmax1, fmaxf(s[t][2], s[t][3]));
        }
        rmax0 = fmaxf(rmax0, __shfl_xor_sync(0xffffffffu, rmax0, 1));
        rmax0 = fmaxf(rmax0, __shfl_xor_sync(0xffffffffu, rmax0, 2));
        rmax1 = fmaxf(rmax1, __shfl_xor_sync(0xffffffffu, rmax1, 1));
        rmax1 = fmaxf(rmax1, __shfl_xor_sync(0xffffffffu, rmax1, 2));
        float mn0 = fmaxf(m0, rmax0), mn1 = fmaxf(m1, rmax1);
        float cr0 = fast_exp(m0 - mn0), cr1 = fast_exp(m1 - mn1);
        float sum0 = 0.0f, sum1 = 0.0f;
#pragma unroll
        for (int t = 0; t < 16; t++) {
            s[t][0] = fast_exp(s[t][0] - mn0);
            s[t][1] = fast_exp(s[t][1] - mn0);
            s[t][2] = fast_exp(s[t][2] - mn1);
            s[t][3] = fast_exp(s[t][3] - mn1);
            sum0 += s[t][0] + s[t][1];
            sum1 += s[t][2] + s[t][3];
        }
        sum0 += __shfl_xor_sync(0xffffffffu, sum0, 1);
        sum0 += __shfl_xor_sync(0xffffffffu, sum0, 2);
        sum1 += __shfl_xor_sync(0xffffffffu, sum1, 1);
        sum1 += __shfl_xor_sync(0xffffffffu, sum1, 2);
        l0 = l0 * cr0 + sum0;
        l1 = l1 * cr1 + sum1;
        m0 = mn0;
        m1 = mn1;
#pragma unroll
        for (int d = 0; d < 8; d++) {
            o[d][0] *= cr0; o[d][1] *= cr0;
            o[d][2] *= cr1; o[d][3] *= cr1;
        }

        // O += P V
#pragma unroll
        for (int jt16 = 0; jt16 < 8; jt16++) {
            uint32_t a[4];
            a[0] = pack_half2(s[jt16 * 2][0], s[jt16 * 2][1]);
            a[1] = pack_half2(s[jt16 * 2][2], s[jt16 * 2][3]);
            a[2] = pack_half2(s[jt16 * 2 + 1][0], s[jt16 * 2 + 1][1]);
            a[3] = pack_half2(s[jt16 * 2 + 1][2], s[jt16 * 2 + 1][3]);
#pragma unroll
            for (int dt16 = 0; dt16 < 4; dt16++) {
                uint32_t v[4];
                ldsm4t(v, &sV[(jt16 * 16 + vrow) * 72 + dt16 * 16 + vcol]);
                mma_f16(o[dt16 * 2], a, v[0], v[1]);
                mma_f16(o[dt16 * 2 + 1], a, v[2], v[3]);
            }
        }

        // Refill the single K/V buffer for the next tile
        if (jt < 7) {
            __syncthreads();               // all reads of this tile done
            LOAD_KV((jt + 1) * 128)
            asm volatile("cp.async.wait_group 0;");
            __syncthreads();               // new tile visible to all
        }
    }
#undef LOAD_KV

    // Epilogue: normalize, split to bf16 hi/lo, write [b*n][h*64+d]
    const float inv0 = 1.0f / l0, inv1 = 1.0f / l1;
    const int b_idx = bh >> 3, h = bh & 7;
    const size_t rowa = (size_t)b_idx * 1024 + i0 + warp * 16 + g;
    const size_t rowb = rowa + 8;
    const int colb = h * 64 + tig * 2;
#pragma unroll
    for (int dt = 0; dt < 8; dt++) {
        int col = colb + dt * 8;
        float v0 = o[dt][0] * inv0, v1 = o[dt][1] * inv0;
        float v2 = o[dt][2] * inv1, v3 = o[dt][3] * inv1;
        __nv_bfloat162 ph, pl;
        ph.x = __float2bfloat16(v0); ph.y = __float2bfloat16(v1);
        pl.x = __float2bfloat16(v0 - __bfloat162float(ph.x));
        pl.y = __float2bfloat16(v1 - __bfloat162float(ph.y));
        *(__nv_bfloat162*)&g_Oh[rowa * 512 + col] = ph;
        *(__nv_bfloat162*)&g_Ol[rowa * 512 + col] = pl;
        ph.x = __float2bfloat16(v2); ph.y = __float2bfloat16(v3);
        pl.x = __float2bfloat16(v2 - __bfloat162float(ph.x));
        pl.y = __float2bfloat16(v3 - __bfloat162float(ph.y));
        *(__nv_bfloat162*)&g_Oh[rowb * 512 + col] = ph;
        *(__nv_bfloat162*)&g_Ol[rowb * 512 + col] = pl;
    }
}

// ---------------------------------------------------------------------------
// Kernel 3: output projection out = O @ w_out + b_out
__global__ __launch_bounds__(256, 2) void out_gemm_mma(const float* __restrict__ bias,
                                                       float* __restrict__ out) {
    extern __shared__ char sm[];
    float c[4][4][4];
#pragma unroll
    for (int a = 0; a < 4; a++)
#pragma unroll
        for (int b = 0; b < 4; b++)
#pragma unroll
            for (int d = 0; d < 4; d++) c[a][b][d] = 0.0f;

    const int row0 = blockIdx.y * 128, col0 = blockIdx.x * 128;
    gemm_loop_bf16(g_Oh, g_Ol, g_woh, g_wol, row0, col0, sm, c);

    const int lane = threadIdx.x & 31, warp = threadIdx.x >> 5;
    const int wy = warp >> 2, wx = warp & 3, g = lane >> 2, tig = lane & 3;
#pragma unroll
    for (int mt = 0; mt < 4; mt++)
#pragma unroll
        for (int nt = 0; nt < 4; nt++) {
            int r = row0 + wy * 64 + mt * 16 + g;
            int cc = col0 + wx * 32 + nt * 8 + tig * 2;
            float b0 = bias[cc], b1 = bias[cc + 1];
            *(float2*)&out[(size_t)r * 512 + cc] =
                make_float2(c[mt][nt][0] + b0, c[mt][nt][1] + b1);
            *(float2*)&out[(size_t)(r + 8) * 512 + cc] =
                make_float2(c[mt][nt][2] + b0, c[mt][nt][3] + b1);
        }
}

// ---------------------------------------------------------------------------
extern "C" void kernel_launch(void* const* d_in, const int* in_sizes, int n_in,
                              void* d_out, int out_size) {
    const float* x     = (const float*)d_in[0];
    const float* w_qkv = (const float*)d_in[1];
    const float* w_out = (const float*)d_in[2];
    const float* b_out = (const float*)d_in[3];
    float* out = (float*)d_out;

    const int gemm_smem = 2 * 4 * 128 * 40 * 2;   // 81920 B (covers Cs 67584)
    const int attn_smem = 5 * 128 * 72 * 2;       // 92160 B
    cudaFuncSetAttribute(qkv_gemm_mma, cudaFuncAttributeMaxDynamicSharedMemorySize, gemm_smem);
    cudaFuncSetAttribute(attn_mma, cudaFuncAttributeMaxDynamicSharedMemorySize, attn_smem);
    cudaFuncSetAttribute(out_gemm_mma, cudaFuncAttributeMaxDynamicSharedMemorySize, gemm_smem);

    prep_x<<<4096, 256>>>(x);
    prep_w<<<dim3(48, 16), 256>>>(w_qkv, 1536, 0);
    prep_w<<<dim3(16, 16), 256>>>(w_out, 512, 1);
    qkv_gemm_mma<<<dim3(12, 64), 256, gemm_smem>>>();
    attn_mma<<<dim3(8, 64), 256, attn_smem>>>();
    out_gemm_mma<<<dim3(4, 64), 256, gemm_smem>>>(b_out, out);
}

// round 11
// speedup vs baseline: 3.0106x; 1.1371x over previous
#include <cuda_runtime.h>
#include <cuda_bf16.h>
#include <cuda_fp16.h>
#include <math.h>
#include <stdint.h>

// ---------------------------------------------------------------------------
// x(8192,512) @ w_qkv(512,1536) -> 64-head attention (n=1024, dh=64,
// scale=8^-0.5) -> @ w_out(512,512) + b_out. fp32 in/out, rel_err < 1e-3.
// Round 11 (no tcgen05 on this toolchain's sm_103 target): mma.sync HMMA.
//  - qkv: bf16x3, chunk-64 single-stage, 2 CTAs/SM
//  - attention: bf16x3 S + fp16 PV (proven), emits O as fp16
//  - out-proj: single-pass fp16 (error budget: +4e-4 RSS -> ~4.5e-4 total)
// ---------------------------------------------------------------------------

__device__ alignas(16) __nv_bfloat16 g_xh[8192 * 512], g_xl[8192 * 512];      // [m][k]
__device__ alignas(16) __nv_bfloat16 g_wqh[1536 * 512], g_wql[1536 * 512];    // [n][k]
__device__ alignas(16) __half        g_wof[512 * 512];                        // [n][k] fp16
__device__ alignas(16) __nv_bfloat16 g_Qh[64 * 1024 * 64], g_Ql[64 * 1024 * 64]; // [bh][n][d]
__device__ alignas(16) __nv_bfloat16 g_Kh[64 * 1024 * 64], g_Kl[64 * 1024 * 64]; // [bh][n][d]
__device__ alignas(16) __half        g_Vf[64 * 1024 * 64];                       // [bh][n][d]
__device__ alignas(16) __half        g_Of[8192 * 512];                           // [b*n][h*64+d]

// ---------------------------------------------------------------------------
__device__ __forceinline__ float fast_exp(float x) {
    float y = x * 1.4426950408889634f;
    y = fmaxf(y, -126.0f);
    y = fminf(y, 126.0f);
    float nf = rintf(y);
    float t = (y - nf) * 0.6931471805599453f;
    float p = 8.3333337e-3f;
    p = fmaf(p, t, 4.1666668e-2f);
    p = fmaf(p, t, 0.16666667f);
    p = fmaf(p, t, 0.5f);
    p = fmaf(p, t, 1.0f);
    p = fmaf(p, t, 1.0f);
    return p * __int_as_float(((int)nf + 127) << 23);
}

// ---------------------------------------------------------------------------
__device__ __forceinline__ uint32_t smem_u32(const void* p) {
    return (uint32_t)__cvta_generic_to_shared(p);
}
__device__ __forceinline__ void ldsm4(uint32_t r[4], const void* p) {
    uint32_t a = smem_u32(p);
    asm volatile("ldmatrix.sync.aligned.m8n8.x4.shared.b16 {%0,%1,%2,%3}, [%4];"
                 : "=r"(r[0]), "=r"(r[1]), "=r"(r[2]), "=r"(r[3]) : "r"(a));
}
__device__ __forceinline__ void ldsm4t(uint32_t r[4], const void* p) {
    uint32_t a = smem_u32(p);
    asm volatile("ldmatrix.sync.aligned.m8n8.x4.trans.shared.b16 {%0,%1,%2,%3}, [%4];"
                 : "=r"(r[0]), "=r"(r[1]), "=r"(r[2]), "=r"(r[3]) : "r"(a));
}
__device__ __forceinline__ void mma_bf16(float c[4], const uint32_t a[4],
                                         uint32_t b0, uint32_t b1) {
    asm volatile(
        "mma.sync.aligned.m16n8k16.row.col.f32.bf16.bf16.f32 "
        "{%0,%1,%2,%3}, {%4,%5,%6,%7}, {%8,%9}, {%0,%1,%2,%3};"
        : "+f"(c[0]), "+f"(c[1]), "+f"(c[2]), "+f"(c[3])
        : "r"(a[0]), "r"(a[1]), "r"(a[2]), "r"(a[3]), "r"(b0), "r"(b1));
}
__device__ __forceinline__ void mma_f16(float c[4], const uint32_t a[4],
                                        uint32_t b0, uint32_t b1) {
    asm volatile(
        "mma.sync.aligned.m16n8k16.row.col.f32.f16.f16.f32 "
        "{%0,%1,%2,%3}, {%4,%5,%6,%7}, {%8,%9}, {%0,%1,%2,%3};"
        : "+f"(c[0]), "+f"(c[1]), "+f"(c[2]), "+f"(c[3])
        : "r"(a[0]), "r"(a[1]), "r"(a[2]), "r"(a[3]), "r"(b0), "r"(b1));
}
__device__ __forceinline__ uint32_t pack_half2(float lo, float hi) {
    __half2 h = __floats2half2_rn(lo, hi);
    return *reinterpret_cast<uint32_t*>(&h);
}
__device__ __forceinline__ void cp16(void* s, const void* g) {
    asm volatile("cp.async.cg.shared.global [%0], [%1], 16;" :: "r"(smem_u32(s)), "l"(g));
}
__device__ __forceinline__ void cp_commit() {
    asm volatile("cp.async.commit_group;");
}

// ---------------------------------------------------------------------------
// Prepasses (device symbols touched only from device code)
__global__ __launch_bounds__(256) void prep_x(const float* __restrict__ x) {
    int i = blockIdx.x * 256 + threadIdx.x;
    float4 v = *(const float4*)&x[(size_t)i * 4];
    alignas(8) __nv_bfloat16 hh[4], ll[4];
    float vv[4] = {v.x, v.y, v.z, v.w};
#pragma unroll
    for (int k = 0; k < 4; k++) {
        hh[k] = __float2bfloat16(vv[k]);
        ll[k] = __float2bfloat16(vv[k] - __bfloat162float(hh[k]));
    }
    *(uint2*)&g_xh[(size_t)i * 4] = *(const uint2*)hh;
    *(uint2*)&g_xl[(size_t)i * 4] = *(const uint2*)ll;
}

__global__ __launch_bounds__(256) void prep_wq(const float* __restrict__ W) {
    __shared__ float tile[32][33];
    const int c0 = blockIdx.x * 32, r0 = blockIdx.y * 32;
    const int tx = threadIdx.x & 31, ty = threadIdx.x >> 5;
#pragma unroll
    for (int i = ty; i < 32; i += 8)
        tile[i][tx] = W[(size_t)(r0 + i) * 1536 + c0 + tx];
    __syncthreads();
#pragma unroll
    for (int i = ty; i < 32; i += 8) {
        float v = tile[tx][i];
        __nv_bfloat16 h = __float2bfloat16(v);
        size_t o = (size_t)(c0 + i) * 512 + r0 + tx;
        g_wqh[o] = h;
        g_wql[o] = __float2bfloat16(v - __bfloat162float(h));
    }
}

__global__ __launch_bounds__(256) void prep_wo(const float* __restrict__ W) {
    __shared__ float tile[32][33];
    const int c0 = blockIdx.x * 32, r0 = blockIdx.y * 32;
    const int tx = threadIdx.x & 31, ty = threadIdx.x >> 5;
#pragma unroll
    for (int i = ty; i < 32; i += 8)
        tile[i][tx] = W[(size_t)(r0 + i) * 512 + c0 + tx];
    __syncthreads();
#pragma unroll
    for (int i = ty; i < 32; i += 8)
        g_wof[(size_t)(c0 + i) * 512 + r0 + tx] = __float2half_rn(tile[tx][i]);
}

// ---------------------------------------------------------------------------
// bf16x3 mainloop: 128x128 tile, K=512, chunk 64, SINGLE stage, 2 CTAs/SM.
// Smem: 4 x [128][72] bf16 = 73728 B.
__device__ __forceinline__ void gemm_loop_bf16(
    const __nv_bfloat16* __restrict__ Ah, const __nv_bfloat16* __restrict__ Al,
    const __nv_bfloat16* __restrict__ Bh, const __nv_bfloat16* __restrict__ Bl,
    int row0, int col0, char* sm, float c[4][4][4]) {
    __nv_bfloat16* sAh = (__nv_bfloat16*)sm;
    __nv_bfloat16* sAl = sAh + 128 * 72;
    __nv_bfloat16* sBh = sAl + 128 * 72;
    __nv_bfloat16* sBl = sBh + 128 * 72;
    const int tid = threadIdx.x, lane = tid & 31, warp = tid >> 5;
    const int wy = warp >> 2, wx = warp & 3;
    const int lr = lane & 15, lc = (lane >> 4) * 8;

    for (int kc = 0; kc < 512; kc += 64) {
#pragma unroll
        for (int i = 0; i < 4; i++) {
            int idx = i * 256 + tid;
            int r = idx >> 3, c8 = (idx & 7) * 8;
            cp16(&sAh[r * 72 + c8], &Ah[(size_t)(row0 + r) * 512 + kc + c8]);
            cp16(&sAl[r * 72 + c8], &Al[(size_t)(row0 + r) * 512 + kc + c8]);
            cp16(&sBh[r * 72 + c8], &Bh[(size_t)(col0 + r) * 512 + kc + c8]);
            cp16(&sBl[r * 72 + c8], &Bl[(size_t)(col0 + r) * 512 + kc + c8]);
        }
        cp_commit();
        asm volatile("cp.async.wait_group 0;");
        __syncthreads();
#pragma unroll
        for (int kt = 0; kt < 4; kt++) {
            uint32_t ah[4][4], al[4][4];
#pragma unroll
            for (int mt = 0; mt < 4; mt++) {
                int ro = (wy * 64 + mt * 16 + lr) * 72 + kt * 16 + lc;
                ldsm4(ah[mt], &sAh[ro]);
                ldsm4(al[mt], &sAl[ro]);
            }
#pragma unroll
            for (int nt16 = 0; nt16 < 2; nt16++) {
                uint32_t bh[4], bl[4];
                int ro = (wx * 32 + nt16 * 16 + lr) * 72 + kt * 16 + lc;
                ldsm4(bh, &sBh[ro]);
                ldsm4(bl, &sBl[ro]);
#pragma unroll
                for (int mt = 0; mt < 4; mt++) {
                    float* c0 = c[mt][nt16 * 2];
                    float* c1 = c[mt][nt16 * 2 + 1];
                    // interleaved chains: c0/c1 alternate (RAW distance 2)
                    mma_bf16(c0, ah[mt], bh[0], bh[2]);
                    mma_bf16(c1, ah[mt], bh[1], bh[3]);
                    mma_bf16(c0, ah[mt], bl[0], bl[2]);
                    mma_bf16(c1, ah[mt], bl[1], bl[3]);
                    mma_bf16(c0, al[mt], bh[0], bh[2]);
                    mma_bf16(c1, al[mt], bh[1], bh[3]);
                }
            }
        }
        __syncthreads();   // protect buffer before next chunk's cp.async
    }
}

// ---------------------------------------------------------------------------
// Kernel 1: QKV projection -> Q/K bf16 hi/lo [bh][n][d] (Q pre-scaled), V fp16
__global__ __launch_bounds__(256, 2) void qkv_gemm_mma() {
    extern __shared__ char sm[];
    float c[4][4][4];
#pragma unroll
    for (int a = 0; a < 4; a++)
#pragma unroll
        for (int b = 0; b < 4; b++)
#pragma unroll
            for (int d = 0; d < 4; d++) c[a][b][d] = 0.0f;

    const int row0 = blockIdx.y * 128, col0 = blockIdx.x * 128;
    gemm_loop_bf16(g_xh, g_xl, g_wqh, g_wql, row0, col0, sm, c);

    float* Cs = (float*)sm;
    __syncthreads();
    const int lane = threadIdx.x & 31, warp = threadIdx.x >> 5;
    const int wy = warp >> 2, wx = warp & 3, g = lane >> 2, tig = lane & 3;
#pragma unroll
    for (int mt = 0; mt < 4; mt++)
#pragma unroll
        for (int nt = 0; nt < 4; nt++) {
            int r = wy * 64 + mt * 16 + g, cc = wx * 32 + nt * 8 + tig * 2;
            Cs[r * 132 + cc] = c[mt][nt][0];
            Cs[r * 132 + cc + 1] = c[mt][nt][1];
            Cs[(r + 8) * 132 + cc] = c[mt][nt][2];
            Cs[(r + 8) * 132 + cc + 1] = c[mt][nt][3];
        }
    __syncthreads();

    const int tid = threadIdx.x;
    const int ty = tid >> 4, tx = tid & 15;
    const int jloc = tx * 8, j0 = col0 + jloc;
    const int h = j0 / 192, part = (j0 % 192) >> 6, d0 = j0 & 63;
    const int rowg0 = row0 + ty * 8;
    const int b_idx = rowg0 >> 10, n0 = rowg0 & 1023, bh = b_idx * 8 + h;
    const float qs = 0.35355339059327373f;   // 8^-0.5 (batch-size scale!)

#pragma unroll
    for (int r = 0; r < 8; r++) {
        float v[8];
#pragma unroll
        for (int k = 0; k < 8; k++) v[k] = Cs[(ty * 8 + r) * 132 + jloc + k];
        size_t base = ((size_t)bh * 1024 + n0 + r) * 64 + d0;
        if (part == 0) {
            alignas(16) __nv_bfloat16 hh[8], ll[8];
#pragma unroll
            for (int k = 0; k < 8; k++) {
                float sv = v[k] * qs;
                hh[k] = __float2bfloat16(sv);
                ll[k] = __float2bfloat16(sv - __bfloat162float(hh[k]));
            }
            *(uint4*)&g_Qh[base] = *(const uint4*)hh;
            *(uint4*)&g_Ql[base] = *(const uint4*)ll;
        } else if (part == 1) {
            alignas(16) __nv_bfloat16 hh[8], ll[8];
#pragma unroll
            for (int k = 0; k < 8; k++) {
                hh[k] = __float2bfloat16(v[k]);
                ll[k] = __float2bfloat16(v[k] - __bfloat162float(hh[k]));
            }
            *(uint4*)&g_Kh[base] = *(const uint4*)hh;
            *(uint4*)&g_Kl[base] = *(const uint4*)ll;
        } else {
            alignas(16) __half hv[8];
#pragma unroll
            for (int k = 0; k < 8; k++) hv[k] = __float2half_rn(v[k]);
            *(uint4*)&g_Vf[base] = *(const uint4*)hv;
        }
    }
}

// ---------------------------------------------------------------------------
// Kernel 2: fused flash attention (round-9 structure), O emitted as fp16.
__global__ __launch_bounds__(256, 2) void attn_mma() {
    extern __shared__ char sm[];
    __nv_bfloat16* sQh = (__nv_bfloat16*)sm;
    __nv_bfloat16* sQl = sQh + 128 * 72;
    __nv_bfloat16* sKh = sQl + 128 * 72;
    __nv_bfloat16* sKl = sKh + 128 * 72;
    __half* sV = (__half*)(sKl + 128 * 72);

    const int tid = threadIdx.x, lane = tid & 31, warp = tid >> 5;
    const int g = lane >> 2, tig = lane & 3;
    const int lr = lane & 15, lc = (lane >> 4) * 8;
    const int vrow = ((lane >> 3) & 1) * 8 + (lane & 7);
    const int vcol = (lane >> 4) * 8;

    const int bh = blockIdx.y;
    const int i0 = blockIdx.x * 128;
    const size_t hb = (size_t)bh * 1024 * 64;

#define LOAD_KV(j0)                                                               \
    {                                                                             \
        _Pragma("unroll") for (int i = 0; i < 4; i++) {                           \
            int idx = i * 256 + tid;                                              \
            int r = idx >> 3, c8 = (idx & 7) * 8;                                 \
            cp16(&sKh[r * 72 + c8], &g_Kh[hb + (size_t)((j0) + r) * 64 + c8]);    \
            cp16(&sKl[r * 72 + c8], &g_Kl[hb + (size_t)((j0) + r) * 64 + c8]);    \
            cp16(&sV[r * 72 + c8],  &g_Vf[hb + (size_t)((j0) + r) * 64 + c8]);    \
        }                                                                         \
        cp_commit();                                                              \
    }

#pragma unroll
    for (int i = 0; i < 4; i++) {
        int idx = i * 256 + tid;
        int r = idx >> 3, c8 = (idx & 7) * 8;
        cp16(&sQh[r * 72 + c8], &g_Qh[hb + (size_t)(i0 + r) * 64 + c8]);
        cp16(&sQl[r * 72 + c8], &g_Ql[hb + (size_t)(i0 + r) * 64 + c8]);
    }
    LOAD_KV(0)
    asm volatile("cp.async.wait_group 0;");
    __syncthreads();

    float o[8][4];
#pragma unroll
    for (int d = 0; d < 8; d++)
#pragma unroll
        for (int k = 0; k < 4; k++) o[d][k] = 0.0f;
    float m0 = -1e30f, m1 = -1e30f, l0 = 0.0f, l1 = 0.0f;

    for (int jt = 0; jt < 8; jt++) {
        float s[16][4];
#pragma unroll
        for (int t = 0; t < 16; t++)
#pragma unroll
            for (int k = 0; k < 4; k++) s[t][k] = 0.0f;

#pragma unroll
        for (int kt = 0; kt < 4; kt++) {
            uint32_t qh[4], ql[4];
            int qo = (warp * 16 + lr) * 72 + kt * 16 + lc;
            ldsm4(qh, &sQh[qo]);
            ldsm4(ql, &sQl[qo]);
#pragma unroll
            for (int nt = 0; nt < 8; nt++) {
                uint32_t kh[4], kl[4];
                int ko = (nt * 16 + lr) * 72 + kt * 16 + lc;
                ldsm4(kh, &sKh[ko]);
                ldsm4(kl, &sKl[ko]);
                float* s0 = s[nt * 2];
                float* s1 = s[nt * 2 + 1];
                // interleaved chains
                mma_bf16(s0, qh, kh[0], kh[2]);
                mma_bf16(s1, qh, kh[1], kh[3]);
                mma_bf16(s0, qh, kl[0], kl[2]);
                mma_bf16(s1, qh, kl[1], kl[3]);
                mma_bf16(s0, ql, kh[0], kh[2]);
                mma_bf16(s1, ql, kh[1], kh[3]);
            }
        }

        float rmax0 = -1e30f, rmax1 = -1e30f;
#pragma unroll
        for (int t = 0; t < 16; t++) {
            rmax0 = fmaxf(rmax0, fmaxf(s[t][0], s[t][1]));
            rmax1 = fmaxf(rmax1, fmaxf(s[t][2], s[t][3]));
        }
        rmax0 = fmaxf(rmax0, __shfl_xor_sync(0xffffffffu, rmax0, 1));
        rmax0 = fmaxf(rmax0, __shfl_xor_sync(0xffffffffu, rmax0, 2));
        rmax1 = fmaxf(rmax1, __shfl_xor_sync(0xffffffffu, rmax1, 1));
        rmax1 = fmaxf(rmax1, __shfl_xor_sync(0xffffffffu, rmax1, 2));
        float mn0 = fmaxf(m0, rmax0), mn1 = fmaxf(m1, rmax1);
        float cr0 = fast_exp(m0 - mn0), cr1 = fast_exp(m1 - mn1);
        float sum0 = 0.0f, sum1 = 0.0f;
#pragma unroll
        for (int t = 0; t < 16; t++) {
            s[t][0] = fast_exp(s[t][0] - mn0);
            s[t][1] = fast_exp(s[t][1] - mn0);
            s[t][2] = fast_exp(s[t][2] - mn1);
            s[t][3] = fast_exp(s[t][3] - mn1);
            sum0 += s[t][0] + s[t][1];
            sum1 += s[t][2] + s[t][3];
        }
        sum0 += __shfl_xor_sync(0xffffffffu, sum0, 1);
        sum0 += __shfl_xor_sync(0xffffffffu, sum0, 2);
        sum1 += __shfl_xor_sync(0xffffffffu, sum1, 1);
        sum1 += __shfl_xor_sync(0xffffffffu, sum1, 2);
        l0 = l0 * cr0 + sum0;
        l1 = l1 * cr1 + sum1;
        m0 = mn0;
        m1 = mn1;
#pragma unroll
        for (int d = 0; d < 8; d++) {
            o[d][0] *= cr0; o[d][1] *= cr0;
            o[d][2] *= cr1; o[d][3] *= cr1;
        }

#pragma unroll
        for (int jt16 = 0; jt16 < 8; jt16++) {
            uint32_t a[4];
            a[0] = pack_half2(s[jt16 * 2][0], s[jt16 * 2][1]);
            a[1] = pack_half2(s[jt16 * 2][2], s[jt16 * 2][3]);
            a[2] = pack_half2(s[jt16 * 2 + 1][0], s[jt16 * 2 + 1][1]);
            a[3] = pack_half2(s[jt16 * 2 + 1][2], s[jt16 * 2 + 1][3]);
#pragma unroll
            for (int dt16 = 0; dt16 < 4; dt16++) {
                uint32_t v[4];
                ldsm4t(v, &sV[(jt16 * 16 + vrow) * 72 + dt16 * 16 + vcol]);
                mma_f16(o[dt16 * 2], a, v[0], v[1]);
                mma_f16(o[dt16 * 2 + 1], a, v[2], v[3]);
            }
        }

        if (jt < 7) {
            __syncthreads();
            LOAD_KV((jt + 1) * 128)
            asm volatile("cp.async.wait_group 0;");
            __syncthreads();
        }
    }
#undef LOAD_KV

    // Epilogue: normalize, write fp16 g_Of [b*n][h*64+d]
    const float inv0 = 1.0f / l0, inv1 = 1.0f / l1;
    const int b_idx = bh >> 3, h = bh & 7;
    const size_t rowa = (size_t)b_idx * 1024 + i0 + warp * 16 + g;
    const size_t rowb = rowa + 8;
    const int colb = h * 64 + tig * 2;
#pragma unroll
    for (int dt = 0; dt < 8; dt++) {
        int col = colb + dt * 8;
        *(__half2*)&g_Of[rowa * 512 + col] =
            __floats2half2_rn(o[dt][0] * inv0, o[dt][1] * inv0);
        *(__half2*)&g_Of[rowb * 512 + col] =
            __floats2half2_rn(o[dt][2] * inv1, o[dt][3] * inv1);
    }
}

// ---------------------------------------------------------------------------
// Kernel 3: out = O @ w_out + b_out  — single-pass fp16, 2-stage pipeline.
// Stage: sA[128][72] + sB[128][72] fp16 = 36864 B; 2 stages = 73728 B.
__global__ __launch_bounds__(256, 2) void out_f16(const float* __restrict__ bias,
                                                  float* __restrict__ out) {
    extern __shared__ char sm[];
    const int STAGE = 2 * 128 * 72 * 2;   // 36864
    float c[4][4][4];
#pragma unroll
    for (int a = 0; a < 4; a++)
#pragma unroll
        for (int b = 0; b < 4; b++)
#pragma unroll
            for (int d = 0; d < 4; d++) c[a][b][d] = 0.0f;

    const int tid = threadIdx.x, lane = tid & 31, warp = tid >> 5;
    const int wy = warp >> 2, wx = warp & 3;
    const int lr = lane & 15, lc = (lane >> 4) * 8;
    const int row0 = blockIdx.y * 128, col0 = blockIdx.x * 128;

#define LOADF(kc, st)                                                             \
    {                                                                             \
        __half* dA = (__half*)(sm + (st) * STAGE);                                \
        __half* dB = dA + 128 * 72;                                               \
        _Pragma("unroll") for (int i = 0; i < 4; i++) {                           \
            int idx = i * 256 + tid;                                              \
            int r = idx >> 3, c8 = (idx & 7) * 8;                                 \
            cp16(&dA[r * 72 + c8], &g_Of[(size_t)(row0 + r) * 512 + (kc) + c8]);  \
            cp16(&dB[r * 72 + c8], &g_wof[(size_t)(col0 + r) * 512 + (kc) + c8]); \
        }                                                                         \
        cp_commit();                                                              \
    }

    LOADF(0, 0)
    for (int ks = 0; ks < 8; ks++) {
        if (ks < 7) {
            LOADF((ks + 1) * 64, (ks + 1) & 1)
            asm volatile("cp.async.wait_group 1;");
        } else {
            asm volatile("cp.async.wait_group 0;");
        }
        __syncthreads();
        __half* sA = (__half*)(sm + (ks & 1) * STAGE);
        __half* sB = sA + 128 * 72;
#pragma unroll
        for (int kt = 0; kt < 4; kt++) {
            uint32_t af[4][4];
#pragma unroll
            for (int mt = 0; mt < 4; mt++)
                ldsm4(af[mt], &sA[(wy * 64 + mt * 16 + lr) * 72 + kt * 16 + lc]);
#pragma unroll
            for (int nt16 = 0; nt16 < 2; nt16++) {
                uint32_t bf[4];
                ldsm4(bf, &sB[(wx * 32 + nt16 * 16 + lr) * 72 + kt * 16 + lc]);
#pragma unroll
                for (int mt = 0; mt < 4; mt++) {
                    mma_f16(c[mt][nt16 * 2], af[mt], bf[0], bf[2]);
                    mma_f16(c[mt][nt16 * 2 + 1], af[mt], bf[1], bf[3]);
                }
            }
        }
        __syncthreads();
    }
#undef LOADF

    const int g = lane >> 2, tig = lane & 3;
#pragma unroll
    for (int mt = 0; mt < 4; mt++)
#pragma unroll
        for (int nt = 0; nt < 4; nt++) {
            int r = row0 + wy * 64 + mt * 16 + g;
            int cc = col0 + wx * 32 + nt * 8 + tig * 2;
            float b0 = bias[cc], b1 = bias[cc + 1];
            *(float2*)&out[(size_t)r * 512 + cc] =
                make_float2(c[mt][nt][0] + b0, c[mt][nt][1] + b1);
            *(float2*)&out[(size_t)(r + 8) * 512 + cc] =
                make_float2(c[mt][nt][2] + b0, c[mt][nt][3] + b1);
        }
}

// ---------------------------------------------------------------------------
extern "C" void kernel_launch(void* const* d_in, const int* in_sizes, int n_in,
                              void* d_out, int out_size) {
    const float* x     = (const float*)d_in[0];
    const float* w_qkv = (const float*)d_in[1];
    const float* w_out = (const float*)d_in[2];
    const float* b_out = (const float*)d_in[3];
    float* out = (float*)d_out;

    const int gemm_smem = 4 * 128 * 72 * 2;   // 73728 B (single stage; covers Cs)
    const int attn_smem = 5 * 128 * 72 * 2;   // 92160 B
    const int outf_smem = 2 * 2 * 128 * 72 * 2; // 73728 B (2 stages)
    cudaFuncSetAttribute(qkv_gemm_mma, cudaFuncAttributeMaxDynamicSharedMemorySize, gemm_smem);
    cudaFuncSetAttribute(attn_mma, cudaFuncAttributeMaxDynamicSharedMemorySize, attn_smem);
    cudaFuncSetAttribute(out_f16, cudaFuncAttributeMaxDynamicSharedMemorySize, outf_smem);

    prep_x<<<4096, 256>>>(x);
    prep_wq<<<dim3(48, 16), 256>>>(w_qkv);
    prep_wo<<<dim3(16, 16), 256>>>(w_out);
    qkv_gemm_mma<<<dim3(12, 64), 256, gemm_smem>>>();
    attn_mma<<<dim3(8, 64), 256, attn_smem>>>();
    out_f16<<<dim3(4, 64), 256, outf_smem>>>(b_out, out);
}

// round 15
// speedup vs baseline: 3.0702x; 1.0198x over previous
#include <cuda_runtime.h>
#include <cuda_bf16.h>
#include <cuda_fp16.h>
#include <math.h>
#include <stdint.h>

// ---------------------------------------------------------------------------
// x(8192,512) @ w_qkv(512,1536) -> 64-head attention (n=1024, dh=64,
// scale=8^-0.5) -> @ w_out(512,512) + b_out. fp32 in/out, rel_err < 1e-3.
// Round 15: qkv & out-proj = round-11 proven verbatim. Attention adds the
// (re-audited, safe) V-double-buffer overlap: K/V(jt+1) loads fly during
// PV(jt) mma.
// ---------------------------------------------------------------------------

__device__ alignas(16) __nv_bfloat16 g_xh[8192 * 512], g_xl[8192 * 512];      // [m][k]
__device__ alignas(16) __nv_bfloat16 g_wqh[1536 * 512], g_wql[1536 * 512];    // [n][k]
__device__ alignas(16) __half        g_wof[512 * 512];                        // [n][k] fp16
__device__ alignas(16) __nv_bfloat16 g_Qh[64 * 1024 * 64], g_Ql[64 * 1024 * 64]; // [bh][n][d]
__device__ alignas(16) __nv_bfloat16 g_Kh[64 * 1024 * 64], g_Kl[64 * 1024 * 64]; // [bh][n][d]
__device__ alignas(16) __half        g_Vf[64 * 1024 * 64];                       // [bh][n][d]
__device__ alignas(16) __half        g_Of[8192 * 512];                           // [b*n][h*64+d]

// ---------------------------------------------------------------------------
__device__ __forceinline__ float fast_exp(float x) {
    float y = x * 1.4426950408889634f;
    y = fmaxf(y, -126.0f);
    y = fminf(y, 126.0f);
    float nf = rintf(y);
    float t = (y - nf) * 0.6931471805599453f;
    float p = 8.3333337e-3f;
    p = fmaf(p, t, 4.1666668e-2f);
    p = fmaf(p, t, 0.16666667f);
    p = fmaf(p, t, 0.5f);
    p = fmaf(p, t, 1.0f);
    p = fmaf(p, t, 1.0f);
    return p * __int_as_float(((int)nf + 127) << 23);
}

// ---------------------------------------------------------------------------
__device__ __forceinline__ uint32_t smem_u32(const void* p) {
    return (uint32_t)__cvta_generic_to_shared(p);
}
__device__ __forceinline__ void ldsm4(uint32_t r[4], const void* p) {
    uint32_t a = smem_u32(p);
    asm volatile("ldmatrix.sync.aligned.m8n8.x4.shared.b16 {%0,%1,%2,%3}, [%4];"
                 : "=r"(r[0]), "=r"(r[1]), "=r"(r[2]), "=r"(r[3]) : "r"(a));
}
__device__ __forceinline__ void ldsm4t(uint32_t r[4], const void* p) {
    uint32_t a = smem_u32(p);
    asm volatile("ldmatrix.sync.aligned.m8n8.x4.trans.shared.b16 {%0,%1,%2,%3}, [%4];"
                 : "=r"(r[0]), "=r"(r[1]), "=r"(r[2]), "=r"(r[3]) : "r"(a));
}
__device__ __forceinline__ void mma_bf16(float c[4], const uint32_t a[4],
                                         uint32_t b0, uint32_t b1) {
    asm volatile(
        "mma.sync.aligned.m16n8k16.row.col.f32.bf16.bf16.f32 "
        "{%0,%1,%2,%3}, {%4,%5,%6,%7}, {%8,%9}, {%0,%1,%2,%3};"
        : "+f"(c[0]), "+f"(c[1]), "+f"(c[2]), "+f"(c[3])
        : "r"(a[0]), "r"(a[1]), "r"(a[2]), "r"(a[3]), "r"(b0), "r"(b1));
}
__device__ __forceinline__ void mma_f16(float c[4], const uint32_t a[4],
                                        uint32_t b0, uint32_t b1) {
    asm volatile(
        "mma.sync.aligned.m16n8k16.row.col.f32.f16.f16.f32 "
        "{%0,%1,%2,%3}, {%4,%5,%6,%7}, {%8,%9}, {%0,%1,%2,%3};"
        : "+f"(c[0]), "+f"(c[1]), "+f"(c[2]), "+f"(c[3])
        : "r"(a[0]), "r"(a[1]), "r"(a[2]), "r"(a[3]), "r"(b0), "r"(b1));
}
__device__ __forceinline__ uint32_t pack_half2(float lo, float hi) {
    __half2 h = __floats2half2_rn(lo, hi);
    return *reinterpret_cast<uint32_t*>(&h);
}
__device__ __forceinline__ void cp16(void* s, const void* g) {
    asm volatile("cp.async.cg.shared.global [%0], [%1], 16;" :: "r"(smem_u32(s)), "l"(g));
}
__device__ __forceinline__ void cp_commit() {
    asm volatile("cp.async.commit_group;");
}

// ---------------------------------------------------------------------------
// Prepasses (device symbols touched only from device code)
__global__ __launch_bounds__(256) void prep_x(const float* __restrict__ x) {
    int i = blockIdx.x * 256 + threadIdx.x;
    float4 v = *(const float4*)&x[(size_t)i * 4];
    alignas(8) __nv_bfloat16 hh[4], ll[4];
    float vv[4] = {v.x, v.y, v.z, v.w};
#pragma unroll
    for (int k = 0; k < 4; k++) {
        hh[k] = __float2bfloat16(vv[k]);
        ll[k] = __float2bfloat16(vv[k] - __bfloat162float(hh[k]));
    }
    *(uint2*)&g_xh[(size_t)i * 4] = *(const uint2*)hh;
    *(uint2*)&g_xl[(size_t)i * 4] = *(const uint2*)ll;
}

__global__ __launch_bounds__(256) void prep_wq(const float* __restrict__ W) {
    __shared__ float tile[32][33];
    const int c0 = blockIdx.x * 32, r0 = blockIdx.y * 32;
    const int tx = threadIdx.x & 31, ty = threadIdx.x >> 5;
#pragma unroll
    for (int i = ty; i < 32; i += 8)
        tile[i][tx] = W[(size_t)(r0 + i) * 1536 + c0 + tx];
    __syncthreads();
#pragma unroll
    for (int i = ty; i < 32; i += 8) {
        float v = tile[tx][i];
        __nv_bfloat16 h = __float2bfloat16(v);
        size_t o = (size_t)(c0 + i) * 512 + r0 + tx;
        g_wqh[o] = h;
        g_wql[o] = __float2bfloat16(v - __bfloat162float(h));
    }
}

__global__ __launch_bounds__(256) void prep_wo(const float* __restrict__ W) {
    __shared__ float tile[32][33];
    const int c0 = blockIdx.x * 32, r0 = blockIdx.y * 32;
    const int tx = threadIdx.x & 31, ty = threadIdx.x >> 5;
#pragma unroll
    for (int i = ty; i < 32; i += 8)
        tile[i][tx] = W[(size_t)(r0 + i) * 512 + c0 + tx];
    __syncthreads();
#pragma unroll
    for (int i = ty; i < 32; i += 8)
        g_wof[(size_t)(c0 + i) * 512 + r0 + tx] = __float2half_rn(tile[tx][i]);
}

// ---------------------------------------------------------------------------
// bf16x3 mainloop (round-11 proven): 128x128, K=512, chunk 64, single stage,
// 2 CTAs/SM. Smem: 4 x [128][72] bf16 = 73728 B.
__device__ __forceinline__ void gemm_loop_bf16(
    const __nv_bfloat16* __restrict__ Ah, const __nv_bfloat16* __restrict__ Al,
    const __nv_bfloat16* __restrict__ Bh, const __nv_bfloat16* __restrict__ Bl,
    int row0, int col0, char* sm, float c[4][4][4]) {
    __nv_bfloat16* sAh = (__nv_bfloat16*)sm;
    __nv_bfloat16* sAl = sAh + 128 * 72;
    __nv_bfloat16* sBh = sAl + 128 * 72;
    __nv_bfloat16* sBl = sBh + 128 * 72;
    const int tid = threadIdx.x, lane = tid & 31, warp = tid >> 5;
    const int wy = warp >> 2, wx = warp & 3;
    const int lr = lane & 15, lc = (lane >> 4) * 8;

    for (int kc = 0; kc < 512; kc += 64) {
#pragma unroll
        for (int i = 0; i < 4; i++) {
            int idx = i * 256 + tid;
            int r = idx >> 3, c8 = (idx & 7) * 8;
            cp16(&sAh[r * 72 + c8], &Ah[(size_t)(row0 + r) * 512 + kc + c8]);
            cp16(&sAl[r * 72 + c8], &Al[(size_t)(row0 + r) * 512 + kc + c8]);
            cp16(&sBh[r * 72 + c8], &Bh[(size_t)(col0 + r) * 512 + kc + c8]);
            cp16(&sBl[r * 72 + c8], &Bl[(size_t)(col0 + r) * 512 + kc + c8]);
        }
        cp_commit();
        asm volatile("cp.async.wait_group 0;");
        __syncthreads();
#pragma unroll
        for (int kt = 0; kt < 4; kt++) {
            uint32_t ah[4][4], al[4][4];
#pragma unroll
            for (int mt = 0; mt < 4; mt++) {
                int ro = (wy * 64 + mt * 16 + lr) * 72 + kt * 16 + lc;
                ldsm4(ah[mt], &sAh[ro]);
                ldsm4(al[mt], &sAl[ro]);
            }
#pragma unroll
            for (int nt16 = 0; nt16 < 2; nt16++) {
                uint32_t bh[4], bl[4];
                int ro = (wx * 32 + nt16 * 16 + lr) * 72 + kt * 16 + lc;
                ldsm4(bh, &sBh[ro]);
                ldsm4(bl, &sBl[ro]);
#pragma unroll
                for (int mt = 0; mt < 4; mt++) {
                    float* c0 = c[mt][nt16 * 2];
                    float* c1 = c[mt][nt16 * 2 + 1];
                    mma_bf16(c0, ah[mt], bh[0], bh[2]);
                    mma_bf16(c1, ah[mt], bh[1], bh[3]);
                    mma_bf16(c0, ah[mt], bl[0], bl[2]);
                    mma_bf16(c1, ah[mt], bl[1], bl[3]);
                    mma_bf16(c0, al[mt], bh[0], bh[2]);
                    mma_bf16(c1, al[mt], bh[1], bh[3]);
                }
            }
        }
        __syncthreads();   // protect buffer before next chunk's cp.async
    }
}

// ---------------------------------------------------------------------------
// Kernel 1: QKV projection (round-11 proven verbatim)
__global__ __launch_bounds__(256, 2) void qkv_gemm_mma() {
    extern __shared__ char sm[];
    float c[4][4][4];
#pragma unroll
    for (int a = 0; a < 4; a++)
#pragma unroll
        for (int b = 0; b < 4; b++)
#pragma unroll
            for (int d = 0; d < 4; d++) c[a][b][d] = 0.0f;

    const int row0 = blockIdx.y * 128, col0 = blockIdx.x * 128;
    gemm_loop_bf16(g_xh, g_xl, g_wqh, g_wql, row0, col0, sm, c);

    float* Cs = (float*)sm;
    __syncthreads();
    const int lane = threadIdx.x & 31, warp = threadIdx.x >> 5;
    const int wy = warp >> 2, wx = warp & 3, g = lane >> 2, tig = lane & 3;
#pragma unroll
    for (int mt = 0; mt < 4; mt++)
#pragma unroll
        for (int nt = 0; nt < 4; nt++) {
            int r = wy * 64 + mt * 16 + g, cc = wx * 32 + nt * 8 + tig * 2;
            Cs[r * 132 + cc] = c[mt][nt][0];
            Cs[r * 132 + cc + 1] = c[mt][nt][1];
            Cs[(r + 8) * 132 + cc] = c[mt][nt][2];
            Cs[(r + 8) * 132 + cc + 1] = c[mt][nt][3];
        }
    __syncthreads();

    const int tid = threadIdx.x;
    const int ty = tid >> 4, tx = tid & 15;
    const int jloc = tx * 8, j0 = col0 + jloc;
    const int h = j0 / 192, part = (j0 % 192) >> 6, d0 = j0 & 63;
    const int rowg0 = row0 + ty * 8;
    const int b_idx = rowg0 >> 10, n0 = rowg0 & 1023, bh = b_idx * 8 + h;
    const float qs = 0.35355339059327373f;   // 8^-0.5 (batch-size scale!)

#pragma unroll
    for (int r = 0; r < 8; r++) {
        float v[8];
#pragma unroll
        for (int k = 0; k < 8; k++) v[k] = Cs[(ty * 8 + r) * 132 + jloc + k];
        size_t base = ((size_t)bh * 1024 + n0 + r) * 64 + d0;
        if (part == 0) {
            alignas(16) __nv_bfloat16 hh[8], ll[8];
#pragma unroll
            for (int k = 0; k < 8; k++) {
                float sv = v[k] * qs;
                hh[k] = __float2bfloat16(sv);
                ll[k] = __float2bfloat16(sv - __bfloat162float(hh[k]));
            }
            *(uint4*)&g_Qh[base] = *(const uint4*)hh;
            *(uint4*)&g_Ql[base] = *(const uint4*)ll;
        } else if (part == 1) {
            alignas(16) __nv_bfloat16 hh[8], ll[8];
#pragma unroll
            for (int k = 0; k < 8; k++) {
                hh[k] = __float2bfloat16(v[k]);
                ll[k] = __float2bfloat16(v[k] - __bfloat162float(hh[k]));
            }
            *(uint4*)&g_Kh[base] = *(const uint4*)hh;
            *(uint4*)&g_Kl[base] = *(const uint4*)ll;
        } else {
            alignas(16) __half hv[8];
#pragma unroll
            for (int k = 0; k < 8; k++) hv[k] = __float2half_rn(v[k]);
            *(uint4*)&g_Vf[base] = *(const uint4*)hv;
        }
    }
}

// ---------------------------------------------------------------------------
// Kernel 2: fused flash attention with V double-buffer overlap.
// K single buffer, V x2: K/V(jt+1) cp.async issued after softmax (all K reads
// consumed by S-mma before the sync), overlapping PV(jt) mma which reads the
// OTHER V buffer. smem = 6 x 128*72*2 = 110592 B -> 2 CTAs/SM.
__global__ __launch_bounds__(256, 2) void attn_mma() {
    extern __shared__ char sm[];
    __nv_bfloat16* sQh = (__nv_bfloat16*)sm;
    __nv_bfloat16* sQl = sQh + 128 * 72;
    __nv_bfloat16* sKh = sQl + 128 * 72;
    __nv_bfloat16* sKl = sKh + 128 * 72;
    __half* sV0 = (__half*)(sKl + 128 * 72);
    __half* sV1 = sV0 + 128 * 72;

    const int tid = threadIdx.x, lane = tid & 31, warp = tid >> 5;
    const int g = lane >> 2, tig = lane & 3;
    const int lr = lane & 15, lc = (lane >> 4) * 8;
    const int vrow = ((lane >> 3) & 1) * 8 + (lane & 7);
    const int vcol = (lane >> 4) * 8;

    const int bh = blockIdx.y;
    const int i0 = blockIdx.x * 128;
    const size_t hb = (size_t)bh * 1024 * 64;

#define LOAD_K(j0)                                                                \
    {                                                                             \
        _Pragma("unroll") for (int i = 0; i < 4; i++) {                           \
            int idx = i * 256 + tid;                                              \
            int r = idx >> 3, c8 = (idx & 7) * 8;                                 \
            cp16(&sKh[r * 72 + c8], &g_Kh[hb + (size_t)((j0) + r) * 64 + c8]);    \
            cp16(&sKl[r * 72 + c8], &g_Kl[hb + (size_t)((j0) + r) * 64 + c8]);    \
        }                                                                         \
    }
#define LOAD_V(j0, dst)                                                           \
    {                                                                             \
        _Pragma("unroll") for (int i = 0; i < 4; i++) {                           \
            int idx = i * 256 + tid;                                              \
            int r = idx >> 3, c8 = (idx & 7) * 8;                                 \
            cp16(&(dst)[r * 72 + c8], &g_Vf[hb + (size_t)((j0) + r) * 64 + c8]);  \
        }                                                                         \
    }

    // prologue: Q + K(0) + V(0)
#pragma unroll
    for (int i = 0; i < 4; i++) {
        int idx = i * 256 + tid;
        int r = idx >> 3, c8 = (idx & 7) * 8;
        cp16(&sQh[r * 72 + c8], &g_Qh[hb + (size_t)(i0 + r) * 64 + c8]);
        cp16(&sQl[r * 72 + c8], &g_Ql[hb + (size_t)(i0 + r) * 64 + c8]);
    }
    LOAD_K(0)
    LOAD_V(0, sV0)
    cp_commit();
    asm volatile("cp.async.wait_group 0;");
    __syncthreads();

    float o[8][4];
#pragma unroll
    for (int d = 0; d < 8; d++)
#pragma unroll
        for (int k = 0; k < 4; k++) o[d][k] = 0.0f;
    float m0 = -1e30f, m1 = -1e30f, l0 = 0.0f, l1 = 0.0f;

    for (int jt = 0; jt < 8; jt++) {
        // ---- S = Q K^T ----
        float s[16][4];
#pragma unroll
        for (int t = 0; t < 16; t++)
#pragma unroll
            for (int k = 0; k < 4; k++) s[t][k] = 0.0f;

#pragma unroll
        for (int kt = 0; kt < 4; kt++) {
            uint32_t qh[4], ql[4];
            int qo = (warp * 16 + lr) * 72 + kt * 16 + lc;
            ldsm4(qh, &sQh[qo]);
            ldsm4(ql, &sQl[qo]);
#pragma unroll
            for (int nt = 0; nt < 8; nt++) {
                uint32_t kh[4], kl[4];
                int ko = (nt * 16 + lr) * 72 + kt * 16 + lc;
                ldsm4(kh, &sKh[ko]);
                ldsm4(kl, &sKl[ko]);
                float* s0 = s[nt * 2];
                float* s1 = s[nt * 2 + 1];
                mma_bf16(s0, qh, kh[0], kh[2]);
                mma_bf16(s1, qh, kh[1], kh[3]);
                mma_bf16(s0, qh, kl[0], kl[2]);
                mma_bf16(s1, qh, kl[1], kl[3]);
                mma_bf16(s0, ql, kh[0], kh[2]);
                mma_bf16(s1, ql, kh[1], kh[3]);
            }
        }

        // ---- online softmax ----
        float rmax0 = -1e30f, rmax1 = -1e30f;
#pragma unroll
        for (int t = 0; t < 16; t++) {
            rmax0 = fmaxf(rmax0, fmaxf(s[t][0], s[t][1]));
            rmax1 = fmaxf(rmax1, fmaxf(s[t][2], s[t][3]));
        }
        rmax0 = fmaxf(rmax0, __shfl_xor_sync(0xffffffffu, rmax0, 1));
        rmax0 = fmaxf(rmax0, __shfl_xor_sync(0xffffffffu, rmax0, 2));
        rmax1 = fmaxf(rmax1, __shfl_xor_sync(0xffffffffu, rmax1, 1));
        rmax1 = fmaxf(rmax1, __shfl_xor_sync(0xffffffffu, rmax1, 2));
        float mn0 = fmaxf(m0, rmax0), mn1 = fmaxf(m1, rmax1);
        float cr0 = fast_exp(m0 - mn0), cr1 = fast_exp(m1 - mn1);
        float sum0 = 0.0f, sum1 = 0.0f;
#pragma unroll
        for (int t = 0; t < 16; t++) {
            s[t][0] = fast_exp(s[t][0] - mn0);
            s[t][1] = fast_exp(s[t][1] - mn0);
            s[t][2] = fast_exp(s[t][2] - mn1);
            s[t][3] = fast_exp(s[t][3] - mn1);
            sum0 += s[t][0] + s[t][1];
            sum1 += s[t][2] + s[t][3];
        }
        sum0 += __shfl_xor_sync(0xffffffffu, sum0, 1);
        sum0 += __shfl_xor_sync(0xffffffffu, sum0, 2);
        sum1 += __shfl_xor_sync(0xffffffffu, sum1, 1);
        sum1 += __shfl_xor_sync(0xffffffffu, sum1, 2);
        l0 = l0 * cr0 + sum0;
        l1 = l1 * cr1 + sum1;
        m0 = mn0;
        m1 = mn1;
#pragma unroll
        for (int d = 0; d < 8; d++) {
            o[d][0] *= cr0; o[d][1] *= cr0;
            o[d][2] *= cr1; o[d][3] *= cr1;
        }

        // ---- all K reads consumed; prefetch K/V(jt+1) overlapping PV ----
        __syncthreads();
        if (jt < 7) {
            LOAD_K((jt + 1) * 128)
            LOAD_V((jt + 1) * 128, ((jt + 1) & 1) ? sV1 : sV0)
            cp_commit();
        }

        // ---- O += P V (reads current V buffer; writes target the other) ----
        __half* sV = (jt & 1) ? sV1 : sV0;
#pragma unroll
        for (int jt16 = 0; jt16 < 8; jt16++) {
            uint32_t a[4];
            a[0] = pack_half2(s[jt16 * 2][0], s[jt16 * 2][1]);
            a[1] = pack_half2(s[jt16 * 2][2], s[jt16 * 2][3]);
            a[2] = pack_half2(s[jt16 * 2 + 1][0], s[jt16 * 2 + 1][1]);
            a[3] = pack_half2(s[jt16 * 2 + 1][2], s[jt16 * 2 + 1][3]);
#pragma unroll
            for (int dt16 = 0; dt16 < 4; dt16++) {
                uint32_t v[4];
                ldsm4t(v, &sV[(jt16 * 16 + vrow) * 72 + dt16 * 16 + vcol]);
                mma_f16(o[dt16 * 2], a, v[0], v[1]);
                mma_f16(o[dt16 * 2 + 1], a, v[2], v[3]);
            }
        }

        if (jt < 7) {
            asm volatile("cp.async.wait_group 0;");
            __syncthreads();
        }
    }
#undef LOAD_K
#undef LOAD_V

    // Epilogue: normalize, write fp16 g_Of [b*n][h*64+d]
    const float inv0 = 1.0f / l0, inv1 = 1.0f / l1;
    const int b_idx = bh >> 3, h = bh & 7;
    const size_t rowa = (size_t)b_idx * 1024 + i0 + warp * 16 + g;
    const size_t rowb = rowa + 8;
    const int colb = h * 64 + tig * 2;
#pragma unroll
    for (int dt = 0; dt < 8; dt++) {
        int col = colb + dt * 8;
        *(__half2*)&g_Of[rowa * 512 + col] =
            __floats2half2_rn(o[dt][0] * inv0, o[dt][1] * inv0);
        *(__half2*)&g_Of[rowb * 512 + col] =
            __floats2half2_rn(o[dt][2] * inv1, o[dt][3] * inv1);
    }
}

// ---------------------------------------------------------------------------
// Kernel 3: out = O @ w_out + b_out — round-11 proven fp16 2-stage verbatim.
__global__ __launch_bounds__(256, 2) void out_f16(const float* __restrict__ bias,
                                                  float* __restrict__ out) {
    extern __shared__ char sm[];
    const int STAGE = 2 * 128 * 72 * 2;   // 36864
    float c[4][4][4];
#pragma unroll
    for (int a = 0; a < 4; a++)
#pragma unroll
        for (int b = 0; b < 4; b++)
#pragma unroll
            for (int d = 0; d < 4; d++) c[a][b][d] = 0.0f;

    const int tid = threadIdx.x, lane = tid & 31, warp = tid >> 5;
    const int wy = warp >> 2, wx = warp & 3;
    const int lr = lane & 15, lc = (lane >> 4) * 8;
    const int row0 = blockIdx.y * 128, col0 = blockIdx.x * 128;

#define LOADF(kc, st)                                                             \
    {                                                                             \
        __half* dA = (__half*)(sm + (st) * STAGE);                                \
        __half* dB = dA + 128 * 72;                                               \
        _Pragma("unroll") for (int i = 0; i < 4; i++) {                           \
            int idx = i * 256 + tid;                                              \
            int r = idx >> 3, c8 = (idx & 7) * 8;                                 \
            cp16(&dA[r * 72 + c8], &g_Of[(size_t)(row0 + r) * 512 + (kc) + c8]);  \
            cp16(&dB[r * 72 + c8], &g_wof[(size_t)(col0 + r) * 512 + (kc) + c8]); \
        }                                                                         \
        cp_commit();                                                              \
    }

    LOADF(0, 0)
    for (int ks = 0; ks < 8; ks++) {
        if (ks < 7) {
            LOADF((ks + 1) * 64, (ks + 1) & 1)
            asm volatile("cp.async.wait_group 1;");
        } else {
            asm volatile("cp.async.wait_group 0;");
        }
        __syncthreads();
        __half* sA = (__half*)(sm + (ks & 1) * STAGE);
        __half* sB = sA + 128 * 72;
#pragma unroll
        for (int kt = 0; kt < 4; kt++) {
            uint32_t af[4][4];
#pragma unroll
            for (int mt = 0; mt < 4; mt++)
                ldsm4(af[mt], &sA[(wy * 64 + mt * 16 + lr) * 72 + kt * 16 + lc]);
#pragma unroll
            for (int nt16 = 0; nt16 < 2; nt16++) {
                uint32_t bf[4];
                ldsm4(bf, &sB[(wx * 32 + nt16 * 16 + lr) * 72 + kt * 16 + lc]);
#pragma unroll
                for (int mt = 0; mt < 4; mt++) {
                    mma_f16(c[mt][nt16 * 2], af[mt], bf[0], bf[2]);
                    mma_f16(c[mt][nt16 * 2 + 1], af[mt], bf[1], bf[3]);
                }
            }
        }
        __syncthreads();
    }
#undef LOADF

    const int g = lane >> 2, tig = lane & 3;
#pragma unroll
    for (int mt = 0; mt < 4; mt++)
#pragma unroll
        for (int nt = 0; nt < 4; nt++) {
            int r = row0 + wy * 64 + mt * 16 + g;
            int cc = col0 + wx * 32 + nt * 8 + tig * 2;
            float b0 = bias[cc], b1 = bias[cc + 1];
            *(float2*)&out[(size_t)r * 512 + cc] =
                make_float2(c[mt][nt][0] + b0, c[mt][nt][1] + b1);
            *(float2*)&out[(size_t)(r + 8) * 512 + cc] =
                make_float2(c[mt][nt][2] + b0, c[mt][nt][3] + b1);
        }
}

// ---------------------------------------------------------------------------
extern "C" void kernel_launch(void* const* d_in, const int* in_sizes, int n_in,
                              void* d_out, int out_size) {
    const float* x     = (const float*)d_in[0];
    const float* w_qkv = (const float*)d_in[1];
    const float* w_out = (const float*)d_in[2];
    const float* b_out = (const float*)d_in[3];
    float* out = (float*)d_out;

    const int gemm_smem = 4 * 128 * 72 * 2;     // 73728 B (covers Cs 67584)
    const int attn_smem = 6 * 128 * 72 * 2;     // 110592 B
    const int outf_smem = 2 * 2 * 128 * 72 * 2; // 73728 B
    cudaFuncSetAttribute(qkv_gemm_mma, cudaFuncAttributeMaxDynamicSharedMemorySize, gemm_smem);
    cudaFuncSetAttribute(attn_mma, cudaFuncAttributeMaxDynamicSharedMemorySize, attn_smem);
    cudaFuncSetAttribute(out_f16, cudaFuncAttributeMaxDynamicSharedMemorySize, outf_smem);

    prep_x<<<4096, 256>>>(x);
    prep_wq<<<dim3(48, 16), 256>>>(w_qkv);
    prep_wo<<<dim3(16, 16), 256>>>(w_out);
    qkv_gemm_mma<<<dim3(12, 64), 256, gemm_smem>>>();
    attn_mma<<<dim3(8, 64), 256, attn_smem>>>();
    out_f16<<<dim3(4, 64), 256, outf_smem>>>(b_out, out);
}